// round 1
// baseline (speedup 1.0000x reference)
#include <cuda_runtime.h>

#define H     128
#define TM    64
#define NT    256
#define NMAX  10001
#define E1MAX 80000
#define E2MAX 80000
#define WCAP  (E1MAX*16)

// ------- scratch (static device globals; no runtime allocation) ----------
__device__ int   g_ptr[NMAX + 2];
__device__ int   g_weik[WCAP];
__device__ int   g_wekj[WCAP];
__device__ int   g_weij[WCAP];
__device__ int   g_wcount;
__device__ float g_U[(size_t)E1MAX * H];
__device__ float g_V[(size_t)E1MAX * H];
__device__ float g_Z[(size_t)E2MAX * H];
__device__ float g_m[(size_t)E2MAX * H];

// ------------------------- zero / init -----------------------------------
__global__ void k_zero(int n) {
    int i = blockIdx.x * blockDim.x + threadIdx.x;
    if (i < n) g_m[i] = 0.f;
    if (i == 0) g_wcount = 0;
}

// out_ptr[v] = lower_bound(src1, v)  (src1 sorted ascending)
__global__ void k_ptr(const int* __restrict__ src1, int E1, const int* __restrict__ nn_p) {
    int v = blockIdx.x * blockDim.x + threadIdx.x;
    int nn = *nn_p;
    if (v > nn || v > NMAX) return;
    int lo = 0, hi = E1;
    while (lo < hi) { int mid = (lo + hi) >> 1; if (src1[mid] < v) lo = mid + 1; else hi = mid; }
    g_ptr[v] = lo;
}

// enumerate wedges: for each e1 edge i->k, pair with outgoing edges k->j,
// keep if i!=j, no self loops, and (i,j) is an e2 edge (binary search on keys)
__global__ void k_wedges(const int* __restrict__ src1, const int* __restrict__ dst1, int E1,
                         const int* __restrict__ src2, const int* __restrict__ dst2, int E2,
                         const int* __restrict__ nn_p) {
    int e = blockIdx.x * blockDim.x + threadIdx.x;
    if (e >= E1) return;
    int s = src1[e], k = dst1[e];
    if (s == k) return;
    long long nn = (long long)(*nn_p);
    int b = g_ptr[k], en = g_ptr[k + 1];
    for (int t = b; t < en; t++) {
        int j = dst1[t];
        if (j == k || j == s) continue;
        long long key = (long long)s * nn + (long long)j;
        int lo = 0, hi = E2;
        while (lo < hi) {
            int mid = (lo + hi) >> 1;
            long long km = (long long)src2[mid] * nn + (long long)dst2[mid];
            if (km < key) lo = mid + 1; else hi = mid;
        }
        if (lo < E2 && (long long)src2[lo] * nn + (long long)dst2[lo] == key) {
            int idx = atomicAdd(&g_wcount, 1);
            if (idx < WCAP) { g_weik[idx] = e; g_wekj[idx] = t; g_weij[idx] = lo; }
        }
    }
}

// ------------------- generic gathered GEMM: out[R x 128] -----------------
struct GSpec {
    const float* base[4];
    const int*   idx[4];   // nullptr -> identity row index
    int          pitch[4];
    int          width[4]; // multiple of 32
    int          wrow[4];  // row offset into W1
    int          nseg;
};

__global__ void __launch_bounds__(NT) k_ggemm(GSpec g, int R, const float* __restrict__ W,
                                              float* __restrict__ out) {
    __shared__ int   s_row[4][TM];
    __shared__ float Ar[TM * 32];
    __shared__ float Bs[32 * H];
    int tid = threadIdx.x;
    int w0 = blockIdx.x * TM;

    for (int s = 0; s < g.nseg; s++)
        for (int r = tid; r < TM; r += NT) {
            int row = w0 + r;
            int gr = 0;
            if (row < R) gr = g.idx[s] ? g.idx[s][row] : row;
            s_row[s][r] = gr;
        }
    __syncthreads();

    float C[4][8];
#pragma unroll
    for (int a = 0; a < 4; a++)
#pragma unroll
        for (int b = 0; b < 8; b++) C[a][b] = 0.f;

    int col_t = tid & 15;
    int row_t = tid >> 4;

    int tot = 0;
    for (int s = 0; s < g.nseg; s++) tot += g.width[s] >> 5;

    int seg = 0, segch = 0;
    for (int kc = 0; kc < tot; kc++) {
        int off = segch * 32;
        const float* base = g.base[seg];
        int pitch = g.pitch[seg];
        int wk = g.wrow[seg] + off;
        // gather A chunk [64 x 32] (coalesced 128B per row)
#pragma unroll
        for (int it = 0; it < 8; it++) {
            int pos = tid + it * NT;
            int r = pos >> 5, kk = pos & 31;
            Ar[r * 32 + kk] = base[(long)s_row[seg][r] * pitch + off + kk];
        }
        // load B chunk [32 x 128] via float4
        const float4* w4 = (const float4*)(W + (long)wk * H);
        float4* b4 = (float4*)Bs;
#pragma unroll
        for (int it = 0; it < 4; it++) {
            int p = tid + it * NT;
            b4[p] = w4[p];
        }
        __syncthreads();
#pragma unroll
        for (int kk = 0; kk < 32; kk++) {
            float a0 = Ar[(row_t * 4 + 0) * 32 + kk];
            float a1 = Ar[(row_t * 4 + 1) * 32 + kk];
            float a2 = Ar[(row_t * 4 + 2) * 32 + kk];
            float a3 = Ar[(row_t * 4 + 3) * 32 + kk];
            float bv[8];
#pragma unroll
            for (int cc = 0; cc < 8; cc++) bv[cc] = Bs[kk * H + col_t + 16 * cc];
#pragma unroll
            for (int cc = 0; cc < 8; cc++) {
                C[0][cc] += a0 * bv[cc];
                C[1][cc] += a1 * bv[cc];
                C[2][cc] += a2 * bv[cc];
                C[3][cc] += a3 * bv[cc];
            }
        }
        __syncthreads();
        segch++;
        if ((segch << 5) >= g.width[seg]) { seg++; segch = 0; }
    }

#pragma unroll
    for (int rr = 0; rr < 4; rr++) {
        int row = w0 + row_t * 4 + rr;
        if (row < R) {
#pragma unroll
            for (int cc = 0; cc < 8; cc++)
                out[(long)row * H + col_t + 16 * cc] = C[rr][cc];
        }
    }
}

// ------- per-wedge: hidden = silu(U+V+Z+c*w864+b1); hidden@W2 -> atomic m --
__global__ void __launch_bounds__(NT) k_wedge(const float* __restrict__ sph,
                                              const float* __restrict__ w1,
                                              const float* __restrict__ b1,
                                              const float* __restrict__ w2,
                                              const float* __restrict__ b2) {
    extern __shared__ float sm[];
    float* Hs = sm;             // TM*H
    float* Bs = sm + TM * H;    // 32*H
    __shared__ int   s_eik[TM], s_ekj[TM], s_eij[TM];
    __shared__ float s_c1[TM];

    int tid = threadIdx.x;
    int Wn = g_wcount; if (Wn > WCAP) Wn = WCAP;
    int w0 = blockIdx.x * TM;
    if (w0 >= Wn) return;

    for (int r = tid; r < TM; r += NT) {
        int row = w0 + r;
        int a = 0, b = 0, c = 0; float cf = 0.f;
        if (row < Wn) {
            a = g_weik[row]; b = g_wekj[row]; c = g_weij[row];
            cf = sph[a * 3 + 1] * sph[b * 3 + 1];
        }
        s_eik[r] = a; s_ekj[r] = b; s_eij[r] = c; s_c1[r] = cf;
    }
    __syncthreads();

    // build hidden tile with SiLU
#pragma unroll
    for (int it = 0; it < (TM * H) / NT; it++) {
        int pos = tid + it * NT;
        int r = pos >> 7, c = pos & 127;
        float v = g_U[(long)s_eik[r] * H + c]
                + g_V[(long)s_ekj[r] * H + c]
                + g_Z[(long)s_eij[r] * H + c]
                + s_c1[r] * w1[864 * H + c] + b1[c];
        Hs[r * H + c] = v / (1.f + __expf(-v));
    }
    __syncthreads();

    float C[4][8];
#pragma unroll
    for (int a = 0; a < 4; a++)
#pragma unroll
        for (int b = 0; b < 8; b++) C[a][b] = 0.f;

    int col_t = tid & 15;
    int row_t = tid >> 4;

    for (int kc = 0; kc < 4; kc++) {
        const float4* w4 = (const float4*)(w2 + (long)kc * 32 * H);
        float4* b4 = (float4*)Bs;
#pragma unroll
        for (int it = 0; it < 4; it++) {
            int p = tid + it * NT;
            b4[p] = w4[p];
        }
        __syncthreads();
#pragma unroll
        for (int kk = 0; kk < 32; kk++) {
            int k = kc * 32 + kk;
            float a0 = Hs[(row_t * 4 + 0) * H + k];
            float a1 = Hs[(row_t * 4 + 1) * H + k];
            float a2 = Hs[(row_t * 4 + 2) * H + k];
            float a3 = Hs[(row_t * 4 + 3) * H + k];
            float bv[8];
#pragma unroll
            for (int cc = 0; cc < 8; cc++) bv[cc] = Bs[kk * H + col_t + 16 * cc];
#pragma unroll
            for (int cc = 0; cc < 8; cc++) {
                C[0][cc] += a0 * bv[cc];
                C[1][cc] += a1 * bv[cc];
                C[2][cc] += a2 * bv[cc];
                C[3][cc] += a3 * bv[cc];
            }
        }
        __syncthreads();
    }

    float b2v[8];
#pragma unroll
    for (int cc = 0; cc < 8; cc++) b2v[cc] = b2[col_t + 16 * cc];

#pragma unroll
    for (int rr = 0; rr < 4; rr++) {
        int r = row_t * 4 + rr;
        if (w0 + r < Wn) {
            long base = (long)s_eij[r] * H;
#pragma unroll
            for (int cc = 0; cc < 8; cc++)
                atomicAdd(&g_m[base + col_t + 16 * cc], C[rr][cc] + b2v[cc]);
        }
    }
}

// ---- gate: out = t_e2 + sigmoid(m@wgw+bgw) * tanh(t_e2@wgt+bgt) ----------
__global__ void __launch_bounds__(NT) k_gate(const float* __restrict__ t_e2,
                                             const float* __restrict__ wgw,
                                             const float* __restrict__ bgw,
                                             const float* __restrict__ wgt,
                                             const float* __restrict__ bgt,
                                             int E2, float* __restrict__ out) {
    extern __shared__ float sm[];
    float* Ms = sm;                  // TM*H
    float* Ts = sm + TM * H;         // TM*H
    float* B1 = sm + 2 * TM * H;     // 32*H
    float* B2 = B1 + 32 * H;         // 32*H
    int tid = threadIdx.x;
    int w0 = blockIdx.x * TM;

#pragma unroll
    for (int it = 0; it < (TM * H) / NT; it++) {
        int pos = tid + it * NT;
        int r = pos >> 7, c = pos & 127;
        int row = w0 + r;
        float mv = 0.f, tv = 0.f;
        if (row < E2) {
            mv = g_m[(long)row * H + c];
            tv = t_e2[(long)row * H + c];
        }
        Ms[r * H + c] = mv;
        Ts[r * H + c] = tv;
    }
    __syncthreads();

    float C1[4][8], C2[4][8];
#pragma unroll
    for (int a = 0; a < 4; a++)
#pragma unroll
        for (int b = 0; b < 8; b++) { C1[a][b] = 0.f; C2[a][b] = 0.f; }

    int col_t = tid & 15;
    int row_t = tid >> 4;

    for (int kc = 0; kc < 4; kc++) {
        const float4* wa = (const float4*)(wgw + (long)kc * 32 * H);
        const float4* wb = (const float4*)(wgt + (long)kc * 32 * H);
        float4* p1 = (float4*)B1;
        float4* p2 = (float4*)B2;
#pragma unroll
        for (int it = 0; it < 4; it++) {
            int p = tid + it * NT;
            p1[p] = wa[p];
            p2[p] = wb[p];
        }
        __syncthreads();
#pragma unroll
        for (int kk = 0; kk < 32; kk++) {
            int k = kc * 32 + kk;
            float a10 = Ms[(row_t * 4 + 0) * H + k];
            float a11 = Ms[(row_t * 4 + 1) * H + k];
            float a12 = Ms[(row_t * 4 + 2) * H + k];
            float a13 = Ms[(row_t * 4 + 3) * H + k];
            float a20 = Ts[(row_t * 4 + 0) * H + k];
            float a21 = Ts[(row_t * 4 + 1) * H + k];
            float a22 = Ts[(row_t * 4 + 2) * H + k];
            float a23 = Ts[(row_t * 4 + 3) * H + k];
#pragma unroll
            for (int cc = 0; cc < 8; cc++) {
                float bv1 = B1[kk * H + col_t + 16 * cc];
                float bv2 = B2[kk * H + col_t + 16 * cc];
                C1[0][cc] += a10 * bv1; C1[1][cc] += a11 * bv1;
                C1[2][cc] += a12 * bv1; C1[3][cc] += a13 * bv1;
                C2[0][cc] += a20 * bv2; C2[1][cc] += a21 * bv2;
                C2[2][cc] += a22 * bv2; C2[3][cc] += a23 * bv2;
            }
        }
        __syncthreads();
    }

    float bgwv[8], bgtv[8];
#pragma unroll
    for (int cc = 0; cc < 8; cc++) {
        bgwv[cc] = bgw[col_t + 16 * cc];
        bgtv[cc] = bgt[col_t + 16 * cc];
    }

#pragma unroll
    for (int rr = 0; rr < 4; rr++) {
        int r = row_t * 4 + rr;
        int row = w0 + r;
        if (row < E2) {
#pragma unroll
            for (int cc = 0; cc < 8; cc++) {
                int col = col_t + 16 * cc;
                float gw = C1[rr][cc] + bgwv[cc];
                float gt = C2[rr][cc] + bgtv[cc];
                float sig = 1.f / (1.f + __expf(-gw));
                float th = tanhf(gt);
                out[(long)row * H + col] = Ts[r * H + col] + sig * th;
            }
        }
    }
}

// --------------------------------------------------------------------------
extern "C" void kernel_launch(void* const* d_in, const int* in_sizes, int n_in,
                              void* d_out, int out_size) {
    const float* t_e2 = (const float*)d_in[0];
    const float* h    = (const float*)d_in[1];
    const int*   ei1  = (const int*)d_in[2];
    const int*   ei2  = (const int*)d_in[3];
    const int*   e1e2 = (const int*)d_in[4];
    const float* rbf1 = (const float*)d_in[7];
    const float* rbf2 = (const float*)d_in[8];
    const float* sph  = (const float*)d_in[9];
    const int*   nn_p = (const int*)d_in[10];
    const float* w1   = (const float*)d_in[11];
    const float* b1   = (const float*)d_in[12];
    const float* w2   = (const float*)d_in[13];
    const float* b2   = (const float*)d_in[14];
    const float* wgw  = (const float*)d_in[15];
    const float* bgw  = (const float*)d_in[16];
    const float* wgt  = (const float*)d_in[17];
    const float* bgt  = (const float*)d_in[18];

    int E1 = in_sizes[4];
    int E2 = in_sizes[0] / H;
    const int* src1 = ei1;
    const int* dst1 = ei1 + E1;
    const int* src2 = ei2;
    const int* dst2 = ei2 + E2;

    float *pU, *pV, *pZ;
    cudaGetSymbolAddress((void**)&pU, g_U);
    cudaGetSymbolAddress((void**)&pV, g_V);
    cudaGetSymbolAddress((void**)&pZ, g_Z);

    static int attr_done = 0;
    cudaFuncSetAttribute(k_wedge, cudaFuncAttributeMaxDynamicSharedMemorySize,
                         (TM * H + 32 * H) * 4);
    cudaFuncSetAttribute(k_gate, cudaFuncAttributeMaxDynamicSharedMemorySize,
                         (2 * TM * H + 2 * 32 * H) * 4);
    (void)attr_done;

    // 1. zero accumulator + wedge counter
    {
        int n = E2 * H;
        k_zero<<<(n + NT - 1) / NT, NT>>>(n);
    }
    // 2. CSR pointer over src1
    k_ptr<<<(NMAX + 1 + NT - 1) / NT, NT>>>(src1, E1, nn_p);
    // 3. wedge enumeration
    k_wedges<<<(E1 + NT - 1) / NT, NT>>>(src1, dst1, E1, src2, dst2, E2, nn_p);

    // 4. per-edge linear projections U, V, Z
    {
        GSpec gu;
        gu.nseg = 4;
        gu.base[0] = t_e2; gu.idx[0] = e1e2;    gu.pitch[0] = H;  gu.width[0] = 128; gu.wrow[0] = 0;
        gu.base[1] = h;    gu.idx[1] = src1;    gu.pitch[1] = H;  gu.width[1] = 128; gu.wrow[1] = 384;
        gu.base[2] = h;    gu.idx[2] = dst1;    gu.pitch[2] = H;  gu.width[2] = 128; gu.wrow[2] = 512;
        gu.base[3] = rbf1; gu.idx[3] = nullptr; gu.pitch[3] = 32; gu.width[3] = 32;  gu.wrow[3] = 768;
        k_ggemm<<<(E1 + TM - 1) / TM, NT>>>(gu, E1, w1, pU);

        GSpec gv;
        gv.nseg = 3;
        gv.base[0] = t_e2; gv.idx[0] = e1e2;    gv.pitch[0] = H;  gv.width[0] = 128; gv.wrow[0] = 128;
        gv.base[1] = h;    gv.idx[1] = dst1;    gv.pitch[1] = H;  gv.width[1] = 128; gv.wrow[1] = 640;
        gv.base[2] = rbf1; gv.idx[2] = nullptr; gv.pitch[2] = 32; gv.width[2] = 32;  gv.wrow[2] = 800;
        gv.base[3] = t_e2; gv.idx[3] = nullptr; gv.pitch[3] = H;  gv.width[3] = 0;   gv.wrow[3] = 0;
        k_ggemm<<<(E1 + TM - 1) / TM, NT>>>(gv, E1, w1, pV);

        GSpec gz;
        gz.nseg = 2;
        gz.base[0] = t_e2; gz.idx[0] = nullptr; gz.pitch[0] = H;  gz.width[0] = 128; gz.wrow[0] = 256;
        gz.base[1] = rbf2; gz.idx[1] = nullptr; gz.pitch[1] = 32; gz.width[1] = 32;  gz.wrow[1] = 832;
        gz.base[2] = t_e2; gz.idx[2] = nullptr; gz.pitch[2] = H;  gz.width[2] = 0;   gz.wrow[2] = 0;
        gz.base[3] = t_e2; gz.idx[3] = nullptr; gz.pitch[3] = H;  gz.width[3] = 0;   gz.wrow[3] = 0;
        k_ggemm<<<(E2 + TM - 1) / TM, NT>>>(gz, E2, w1, pZ);
    }

    // 5. wedge MLP + segment-sum (upper-bound grid; blocks past wcount exit)
    {
        long maxw = (long)E1 * 16;
        int blocks = (int)((maxw + TM - 1) / TM);
        size_t smem = (size_t)(TM * H + 32 * H) * 4;
        k_wedge<<<blocks, NT, smem>>>(sph, w1, b1, w2, b2);
    }

    // 6. gated output
    {
        size_t smem = (size_t)(2 * TM * H + 2 * 32 * H) * 4;
        k_gate<<<(E2 + TM - 1) / TM, NT, smem>>>(t_e2, wgw, bgw, wgt, bgt, E2,
                                                 (float*)d_out);
    }
}

// round 2
// speedup vs baseline: 1.6075x; 1.6075x over previous
#include <cuda_runtime.h>

#define H     128
#define NT    256
#define NMAX  10001
#define E1MAX 80000
#define E2MAX 80000
#define WCAP  (E1MAX*16)

// ------- scratch (static device globals; no runtime allocation) ----------
__device__ int   g_ptr[NMAX + 2];
__device__ int   g_cnt[E2MAX];
__device__ int   g_wptr[E2MAX + 1];
__device__ int   g_weik[WCAP];
__device__ int   g_wekj[WCAP];
__device__ float g_U[(size_t)E1MAX * H];
__device__ float g_V[(size_t)E1MAX * H];
__device__ float g_Z[(size_t)E2MAX * H];
__device__ float g_S[(size_t)E2MAX * H];

// ------------------------- helpers ---------------------------------------
__device__ __forceinline__ float to_tf32(float x) {
    unsigned u;
    asm("cvt.rna.tf32.f32 %0, %1;" : "=r"(u) : "f"(x));
    return __uint_as_float(u);
}

__device__ __forceinline__ void mma_tf32(float c[4], const unsigned a[4],
                                         unsigned b0, unsigned b1) {
    asm volatile(
        "mma.sync.aligned.m16n8k8.row.col.f32.tf32.tf32.f32 "
        "{%0,%1,%2,%3}, {%4,%5,%6,%7}, {%8,%9}, {%0,%1,%2,%3};"
        : "+f"(c[0]), "+f"(c[1]), "+f"(c[2]), "+f"(c[3])
        : "r"(a[0]), "r"(a[1]), "r"(a[2]), "r"(a[3]), "r"(b0), "r"(b1));
}

// ---------------- CSR ptr: g_ptr[v] = lower_bound(src1, v) ---------------
__global__ void k_ptr(const int* __restrict__ src1, int E1, const int* __restrict__ nn_p) {
    int v = blockIdx.x * blockDim.x + threadIdx.x;
    int nn = *nn_p;
    if (v > nn || v > NMAX) return;
    int lo = 0, hi = E1;
    while (lo < hi) { int mid = (lo + hi) >> 1; if (src1[mid] < v) lo = mid + 1; else hi = mid; }
    g_ptr[v] = lo;
}

// ------------- per-e2-edge wedge count (sorted-by-eij build) --------------
__global__ void k_count(const int* __restrict__ src2, const int* __restrict__ dst2,
                        const int* __restrict__ dst1, int E2) {
    int q = blockIdx.x * blockDim.x + threadIdx.x;
    if (q >= E2) return;
    int i = src2[q], j = dst2[q];
    int c = 0;
    if (i != j) {
        int b0 = g_ptr[i], e0 = g_ptr[i + 1];
        for (int t = b0; t < e0; t++) {
            int k = dst1[t];
            if (k == i || k == j) continue;
            int b1 = g_ptr[k], e1 = g_ptr[k + 1];
            for (int u = b1; u < e1; u++)
                if (dst1[u] == j) c++;
        }
    }
    g_cnt[q] = c;
}

// single-block exclusive scan over g_cnt -> g_wptr
__global__ void k_scan(int n) {
    __shared__ int wsum[32];
    __shared__ int carry;
    int tid = threadIdx.x, lane = tid & 31, wid = tid >> 5;
    int NTH = blockDim.x;
    if (tid == 0) carry = 0;
    __syncthreads();
    for (int base = 0; base < n; base += NTH) {
        int i = base + tid;
        int v = (i < n) ? g_cnt[i] : 0;
        int x = v;
#pragma unroll
        for (int off = 1; off < 32; off <<= 1) {
            int t = __shfl_up_sync(0xffffffffu, x, off);
            if (lane >= off) x += t;
        }
        if (lane == 31) wsum[wid] = x;
        __syncthreads();
        if (wid == 0) {
            int s = (lane < NTH / 32) ? wsum[lane] : 0;
#pragma unroll
            for (int off = 1; off < 32; off <<= 1) {
                int t = __shfl_up_sync(0xffffffffu, s, off);
                if (lane >= off) s += t;
            }
            wsum[lane] = s;
        }
        __syncthreads();
        int woff = (wid > 0) ? wsum[wid - 1] : 0;
        int incl = x + woff;
        if (i < n) g_wptr[i] = carry + incl - v;
        int total = wsum[(NTH / 32) - 1];
        __syncthreads();
        if (tid == 0) carry += total;
        __syncthreads();
    }
    if (threadIdx.x == 0) g_wptr[n] = carry;
}

__global__ void k_fill(const int* __restrict__ src2, const int* __restrict__ dst2,
                       const int* __restrict__ dst1, int E2) {
    int q = blockIdx.x * blockDim.x + threadIdx.x;
    if (q >= E2) return;
    int i = src2[q], j = dst2[q];
    if (i == j) return;
    int pos = g_wptr[q];
    int b0 = g_ptr[i], e0 = g_ptr[i + 1];
    for (int t = b0; t < e0; t++) {
        int k = dst1[t];
        if (k == i || k == j) continue;
        int b1 = g_ptr[k], e1 = g_ptr[k + 1];
        for (int u = b1; u < e1; u++)
            if (dst1[u] == j) {
                if (pos < WCAP) { g_weik[pos] = t; g_wekj[pos] = u; }
                pos++;
            }
    }
}

// -------------- gathered tf32-MMA GEMM: out[R x 128] ----------------------
struct GSpec {
    const float* base[4];
    const int*   idx[4];   // nullptr -> identity row index
    int          pitch[4];
    int          width[4]; // multiple of 32
    int          wrow[4];  // row offset into W1
    int          nseg;
};

__global__ void __launch_bounds__(NT) k_proj(GSpec g, int R, const float* __restrict__ W,
                                             float* __restrict__ out) {
    __shared__ float As[64][33];
    __shared__ float Bs[32][132];
    __shared__ int   s_row[4][64];
    int tid = threadIdx.x, lane = tid & 31, wid = tid >> 5;
    int warp_m = wid & 1, warp_n = wid >> 1;  // 2 x 4 warp grid (32x32 tiles)
    int m0 = blockIdx.x * 64;

    for (int s = 0; s < g.nseg; s++)
        for (int r = tid; r < 64; r += NT) {
            int row = m0 + r;
            s_row[s][r] = (row < R) ? (g.idx[s] ? g.idx[s][row] : row) : 0;
        }
    __syncthreads();

    float C[2][4][4] = {};
    int tot = 0;
    for (int s = 0; s < g.nseg; s++) tot += g.width[s] >> 5;

    int seg = 0, segch = 0;
    for (int kc = 0; kc < tot; kc++) {
        int off = segch * 32;
        const float* base = g.base[seg];
        int pitch = g.pitch[seg];
        const float* Wc = W + (size_t)(g.wrow[seg] + off) * H;
#pragma unroll
        for (int it = 0; it < 8; it++) {
            int pos = tid + it * NT;
            int r = pos >> 5, c = pos & 31;
            As[r][c] = to_tf32(base[(size_t)s_row[seg][r] * pitch + off + c]);
        }
#pragma unroll
        for (int it = 0; it < 16; it++) {
            int pos = tid + it * NT;
            int r = pos >> 7, c = pos & 127;
            Bs[r][c] = to_tf32(Wc[pos]);
        }
        __syncthreads();
#pragma unroll
        for (int ks = 0; ks < 4; ks++) {
            int k0 = ks * 8;
            unsigned a[2][4];
#pragma unroll
            for (int mt = 0; mt < 2; mt++) {
                int rb = warp_m * 32 + mt * 16 + (lane >> 2);
                int cb = k0 + (lane & 3);
                a[mt][0] = __float_as_uint(As[rb][cb]);
                a[mt][1] = __float_as_uint(As[rb + 8][cb]);
                a[mt][2] = __float_as_uint(As[rb][cb + 4]);
                a[mt][3] = __float_as_uint(As[rb + 8][cb + 4]);
            }
#pragma unroll
            for (int nt = 0; nt < 4; nt++) {
                int nb = warp_n * 32 + nt * 8 + (lane >> 2);
                unsigned b0 = __float_as_uint(Bs[k0 + (lane & 3)][nb]);
                unsigned b1 = __float_as_uint(Bs[k0 + (lane & 3) + 4][nb]);
                mma_tf32(C[0][nt], a[0], b0, b1);
                mma_tf32(C[1][nt], a[1], b0, b1);
            }
        }
        __syncthreads();
        segch++;
        if ((segch << 5) >= g.width[seg]) { seg++; segch = 0; }
    }

#pragma unroll
    for (int mt = 0; mt < 2; mt++) {
        int r0 = warp_m * 32 + mt * 16 + (lane >> 2);
#pragma unroll
        for (int nt = 0; nt < 4; nt++) {
            int cb = warp_n * 32 + nt * 8 + 2 * (lane & 3);
            int row = m0 + r0;
            if (row < R) {
                float2 v = make_float2(C[mt][nt][0], C[mt][nt][1]);
                *(float2*)&out[(size_t)row * H + cb] = v;
            }
            if (row + 8 < R) {
                float2 v = make_float2(C[mt][nt][2], C[mt][nt][3]);
                *(float2*)&out[(size_t)(row + 8) * H + cb] = v;
            }
        }
    }
}

// ---- per-e2 hidden sum: S[q] = sum_w silu(U[eik]+V[ekj]+Z[q]+c*w864+b1) ---
__global__ void __launch_bounds__(NT) k_hsum(const float* __restrict__ sph,
                                             const float* __restrict__ w1,
                                             const float* __restrict__ b1, int E2) {
    int warp = (blockIdx.x * blockDim.x + threadIdx.x) >> 5;
    int lane = threadIdx.x & 31;
    if (warp >= E2) return;
    int q = warp;
    int beg = g_wptr[q], end = g_wptr[q + 1];
    if (beg > WCAP) beg = WCAP;
    if (end > WCAP) end = WCAP;
    float4 z  = *(const float4*)&g_Z[(size_t)q * H + lane * 4];
    float4 w8 = *(const float4*)&w1[(size_t)864 * H + lane * 4];
    float4 bb = *(const float4*)&b1[lane * 4];
    float4 acc = make_float4(0.f, 0.f, 0.f, 0.f);
    for (int w = beg; w < end; w++) {
        int eik = g_weik[w], ekj = g_wekj[w];
        float cf = sph[eik * 3 + 1] * sph[ekj * 3 + 1];
        float4 u = *(const float4*)&g_U[(size_t)eik * H + lane * 4];
        float4 v = *(const float4*)&g_V[(size_t)ekj * H + lane * 4];
        float x;
        x = u.x + v.x + z.x + cf * w8.x + bb.x; acc.x += x / (1.f + __expf(-x));
        x = u.y + v.y + z.y + cf * w8.y + bb.y; acc.y += x / (1.f + __expf(-x));
        x = u.z + v.z + z.z + cf * w8.z + bb.z; acc.z += x / (1.f + __expf(-x));
        x = u.w + v.w + z.w + cf * w8.w + bb.w; acc.w += x / (1.f + __expf(-x));
    }
    *(float4*)&g_S[(size_t)q * H + lane * 4] = acc;
}

// ---- fused: m = S@W2 + cnt*b2; out = t + sigmoid(m@wgw+bgw)*tanh(t@wgt+bgt)
__global__ void __launch_bounds__(NT) k_final(const float* __restrict__ t_e2,
                                              const float* __restrict__ w2,
                                              const float* __restrict__ b2,
                                              const float* __restrict__ wgw,
                                              const float* __restrict__ bgw,
                                              const float* __restrict__ wgt,
                                              const float* __restrict__ bgt,
                                              int E2, float* __restrict__ out) {
    extern __shared__ float sm[];
    float(*Ss)[132] = (float(*)[132])sm;               // 64 x 132 (A buffer: S, then t)
    float(*Ms)[132] = (float(*)[132])(sm + 64 * 132);  // 64 x 132 (m, tf32)
    float(*Bs)[132] = (float(*)[132])(sm + 2 * 64 * 132);  // 32 x 132 weight chunk
    __shared__ int s_cnt[64];

    int tid = threadIdx.x, lane = tid & 31, wid = tid >> 5;
    int warp_m = wid & 1, warp_n = wid >> 1;
    int m0 = blockIdx.x * 64;

    for (int r = tid; r < 64; r += NT) {
        int row = m0 + r;
        s_cnt[r] = (row < E2) ? (g_wptr[row + 1] - g_wptr[row]) : 0;
    }
    // load S tile
#pragma unroll
    for (int it = 0; it < 8; it++) {
        int pos = tid + it * NT;
        int r = pos >> 5, c4 = pos & 31;
        int row = m0 + r;
        float4 v = (row < E2) ? *(const float4*)&g_S[(size_t)row * H + c4 * 4]
                              : make_float4(0.f, 0.f, 0.f, 0.f);
        Ss[r][c4 * 4 + 0] = to_tf32(v.x);
        Ss[r][c4 * 4 + 1] = to_tf32(v.y);
        Ss[r][c4 * 4 + 2] = to_tf32(v.z);
        Ss[r][c4 * 4 + 3] = to_tf32(v.w);
    }
    __syncthreads();

    // ---- stage 1: C = S @ W2 ----
    float C[2][4][4] = {};
    for (int kc = 0; kc < 4; kc++) {
        const float* Wc = w2 + (size_t)kc * 32 * H;
#pragma unroll
        for (int it = 0; it < 16; it++) {
            int pos = tid + it * NT;
            int r = pos >> 7, c = pos & 127;
            Bs[r][c] = to_tf32(Wc[pos]);
        }
        __syncthreads();
#pragma unroll
        for (int ks = 0; ks < 4; ks++) {
            int k0 = kc * 32 + ks * 8;
            int kb = ks * 8;
            unsigned a[2][4];
#pragma unroll
            for (int mt = 0; mt < 2; mt++) {
                int rb = warp_m * 32 + mt * 16 + (lane >> 2);
                int cb = k0 + (lane & 3);
                a[mt][0] = __float_as_uint(Ss[rb][cb]);
                a[mt][1] = __float_as_uint(Ss[rb + 8][cb]);
                a[mt][2] = __float_as_uint(Ss[rb][cb + 4]);
                a[mt][3] = __float_as_uint(Ss[rb + 8][cb + 4]);
            }
#pragma unroll
            for (int nt = 0; nt < 4; nt++) {
                int nb = warp_n * 32 + nt * 8 + (lane >> 2);
                unsigned b0 = __float_as_uint(Bs[kb + (lane & 3)][nb]);
                unsigned b1 = __float_as_uint(Bs[kb + (lane & 3) + 4][nb]);
                mma_tf32(C[0][nt], a[0], b0, b1);
                mma_tf32(C[1][nt], a[1], b0, b1);
            }
        }
        __syncthreads();
    }

    // write Ms = tf32(m = C + cnt*b2); reload Ss with t tile
#pragma unroll
    for (int mt = 0; mt < 2; mt++) {
        int r0 = warp_m * 32 + mt * 16 + (lane >> 2);
        float cn0 = (float)s_cnt[r0], cn1 = (float)s_cnt[r0 + 8];
#pragma unroll
        for (int nt = 0; nt < 4; nt++) {
            int cb = warp_n * 32 + nt * 8 + 2 * (lane & 3);
            Ms[r0][cb]         = to_tf32(C[mt][nt][0] + cn0 * b2[cb]);
            Ms[r0][cb + 1]     = to_tf32(C[mt][nt][1] + cn0 * b2[cb + 1]);
            Ms[r0 + 8][cb]     = to_tf32(C[mt][nt][2] + cn1 * b2[cb]);
            Ms[r0 + 8][cb + 1] = to_tf32(C[mt][nt][3] + cn1 * b2[cb + 1]);
        }
    }
#pragma unroll
    for (int it = 0; it < 8; it++) {
        int pos = tid + it * NT;
        int r = pos >> 5, c4 = pos & 31;
        int row = m0 + r;
        float4 v = (row < E2) ? *(const float4*)&t_e2[(size_t)row * H + c4 * 4]
                              : make_float4(0.f, 0.f, 0.f, 0.f);
        Ss[r][c4 * 4 + 0] = to_tf32(v.x);
        Ss[r][c4 * 4 + 1] = to_tf32(v.y);
        Ss[r][c4 * 4 + 2] = to_tf32(v.z);
        Ss[r][c4 * 4 + 3] = to_tf32(v.w);
    }
    __syncthreads();

    // ---- stage 2a: C2 = m @ wgw ----
    float C2[2][4][4] = {};
    for (int kc = 0; kc < 4; kc++) {
        const float* Wc = wgw + (size_t)kc * 32 * H;
#pragma unroll
        for (int it = 0; it < 16; it++) {
            int pos = tid + it * NT;
            int r = pos >> 7, c = pos & 127;
            Bs[r][c] = to_tf32(Wc[pos]);
        }
        __syncthreads();
#pragma unroll
        for (int ks = 0; ks < 4; ks++) {
            int k0 = kc * 32 + ks * 8;
            int kb = ks * 8;
            unsigned a[2][4];
#pragma unroll
            for (int mt = 0; mt < 2; mt++) {
                int rb = warp_m * 32 + mt * 16 + (lane >> 2);
                int cb = k0 + (lane & 3);
                a[mt][0] = __float_as_uint(Ms[rb][cb]);
                a[mt][1] = __float_as_uint(Ms[rb + 8][cb]);
                a[mt][2] = __float_as_uint(Ms[rb][cb + 4]);
                a[mt][3] = __float_as_uint(Ms[rb + 8][cb + 4]);
            }
#pragma unroll
            for (int nt = 0; nt < 4; nt++) {
                int nb = warp_n * 32 + nt * 8 + (lane >> 2);
                unsigned b0 = __float_as_uint(Bs[kb + (lane & 3)][nb]);
                unsigned b1 = __float_as_uint(Bs[kb + (lane & 3) + 4][nb]);
                mma_tf32(C2[0][nt], a[0], b0, b1);
                mma_tf32(C2[1][nt], a[1], b0, b1);
            }
        }
        __syncthreads();
    }

    // ---- stage 2b: C3 = t @ wgt ----
    float C3[2][4][4] = {};
    for (int kc = 0; kc < 4; kc++) {
        const float* Wc = wgt + (size_t)kc * 32 * H;
#pragma unroll
        for (int it = 0; it < 16; it++) {
            int pos = tid + it * NT;
            int r = pos >> 7, c = pos & 127;
            Bs[r][c] = to_tf32(Wc[pos]);
        }
        __syncthreads();
#pragma unroll
        for (int ks = 0; ks < 4; ks++) {
            int k0 = kc * 32 + ks * 8;
            int kb = ks * 8;
            unsigned a[2][4];
#pragma unroll
            for (int mt = 0; mt < 2; mt++) {
                int rb = warp_m * 32 + mt * 16 + (lane >> 2);
                int cb = k0 + (lane & 3);
                a[mt][0] = __float_as_uint(Ss[rb][cb]);
                a[mt][1] = __float_as_uint(Ss[rb + 8][cb]);
                a[mt][2] = __float_as_uint(Ss[rb][cb + 4]);
                a[mt][3] = __float_as_uint(Ss[rb + 8][cb + 4]);
            }
#pragma unroll
            for (int nt = 0; nt < 4; nt++) {
                int nb = warp_n * 32 + nt * 8 + (lane >> 2);
                unsigned b0 = __float_as_uint(Bs[kb + (lane & 3)][nb]);
                unsigned b1 = __float_as_uint(Bs[kb + (lane & 3) + 4][nb]);
                mma_tf32(C3[0][nt], a[0], b0, b1);
                mma_tf32(C3[1][nt], a[1], b0, b1);
            }
        }
        __syncthreads();
    }

    // ---- epilogue: out = t + sigmoid(C2+bgw)*tanh(C3+bgt) ----
#pragma unroll
    for (int mt = 0; mt < 2; mt++) {
        int r0 = warp_m * 32 + mt * 16 + (lane >> 2);
#pragma unroll
        for (int nt = 0; nt < 4; nt++) {
            int cb = warp_n * 32 + nt * 8 + 2 * (lane & 3);
#pragma unroll
            for (int half = 0; half < 2; half++) {
                int row = m0 + r0 + half * 8;
                if (row >= E2) continue;
#pragma unroll
                for (int e = 0; e < 2; e++) {
                    int col = cb + e;
                    float gw = C2[mt][nt][half * 2 + e] + bgw[col];
                    float gt = C3[mt][nt][half * 2 + e] + bgt[col];
                    float sig = 1.f / (1.f + __expf(-gw));
                    out[(size_t)row * H + col] =
                        t_e2[(size_t)row * H + col] + sig * tanhf(gt);
                }
            }
        }
    }
}

// --------------------------------------------------------------------------
extern "C" void kernel_launch(void* const* d_in, const int* in_sizes, int n_in,
                              void* d_out, int out_size) {
    const float* t_e2 = (const float*)d_in[0];
    const float* h    = (const float*)d_in[1];
    const int*   ei1  = (const int*)d_in[2];
    const int*   ei2  = (const int*)d_in[3];
    const int*   e1e2 = (const int*)d_in[4];
    const float* rbf1 = (const float*)d_in[7];
    const float* rbf2 = (const float*)d_in[8];
    const float* sph  = (const float*)d_in[9];
    const int*   nn_p = (const int*)d_in[10];
    const float* w1   = (const float*)d_in[11];
    const float* b1   = (const float*)d_in[12];
    const float* w2   = (const float*)d_in[13];
    const float* b2   = (const float*)d_in[14];
    const float* wgw  = (const float*)d_in[15];
    const float* bgw  = (const float*)d_in[16];
    const float* wgt  = (const float*)d_in[17];
    const float* bgt  = (const float*)d_in[18];

    int E1 = in_sizes[4];
    int E2 = in_sizes[0] / H;
    const int* src1 = ei1;
    const int* dst1 = ei1 + E1;
    const int* src2 = ei2;
    const int* dst2 = ei2 + E2;

    float *pU, *pV, *pZ;
    cudaGetSymbolAddress((void**)&pU, g_U);
    cudaGetSymbolAddress((void**)&pV, g_V);
    cudaGetSymbolAddress((void**)&pZ, g_Z);

    size_t fsmem = (size_t)(2 * 64 * 132 + 32 * 132) * 4;
    cudaFuncSetAttribute(k_final, cudaFuncAttributeMaxDynamicSharedMemorySize, (int)fsmem);

    // 1. CSR ptr over src1 (sorted)
    k_ptr<<<(NMAX + 1 + NT - 1) / NT, NT>>>(src1, E1, nn_p);
    // 2-4. wedge lists grouped by e2 edge: count -> scan -> fill
    k_count<<<(E2 + NT - 1) / NT, NT>>>(src2, dst2, dst1, E2);
    k_scan<<<1, 1024>>>(E2);
    k_fill<<<(E2 + NT - 1) / NT, NT>>>(src2, dst2, dst1, E2);

    // 5. per-edge projections U, V, Z (tf32 tensor-core GEMMs)
    {
        GSpec gu;
        gu.nseg = 4;
        gu.base[0] = t_e2; gu.idx[0] = e1e2;    gu.pitch[0] = H;  gu.width[0] = 128; gu.wrow[0] = 0;
        gu.base[1] = h;    gu.idx[1] = src1;    gu.pitch[1] = H;  gu.width[1] = 128; gu.wrow[1] = 384;
        gu.base[2] = h;    gu.idx[2] = dst1;    gu.pitch[2] = H;  gu.width[2] = 128; gu.wrow[2] = 512;
        gu.base[3] = rbf1; gu.idx[3] = nullptr; gu.pitch[3] = 32; gu.width[3] = 32;  gu.wrow[3] = 768;
        k_proj<<<(E1 + 63) / 64, NT>>>(gu, E1, w1, pU);

        GSpec gv;
        gv.nseg = 3;
        gv.base[0] = t_e2; gv.idx[0] = e1e2;    gv.pitch[0] = H;  gv.width[0] = 128; gv.wrow[0] = 128;
        gv.base[1] = h;    gv.idx[1] = dst1;    gv.pitch[1] = H;  gv.width[1] = 128; gv.wrow[1] = 640;
        gv.base[2] = rbf1; gv.idx[2] = nullptr; gv.pitch[2] = 32; gv.width[2] = 32;  gv.wrow[2] = 800;
        gv.base[3] = t_e2; gv.idx[3] = nullptr; gv.pitch[3] = H;  gv.width[3] = 0;   gv.wrow[3] = 0;
        k_proj<<<(E1 + 63) / 64, NT>>>(gv, E1, w1, pV);

        GSpec gz;
        gz.nseg = 2;
        gz.base[0] = t_e2; gz.idx[0] = nullptr; gz.pitch[0] = H;  gz.width[0] = 128; gz.wrow[0] = 256;
        gz.base[1] = rbf2; gz.idx[1] = nullptr; gz.pitch[1] = 32; gz.width[1] = 32;  gz.wrow[1] = 832;
        gz.base[2] = t_e2; gz.idx[2] = nullptr; gz.pitch[2] = H;  gz.width[2] = 0;   gz.wrow[2] = 0;
        gz.base[3] = t_e2; gz.idx[3] = nullptr; gz.pitch[3] = H;  gz.width[3] = 0;   gz.wrow[3] = 0;
        k_proj<<<(E2 + 63) / 64, NT>>>(gz, E2, w1, pZ);
    }

    // 6. per-e2 hidden sum (atomic-free segment sum BEFORE the W2 GEMM)
    {
        int warps = E2;
        int blocks = (warps * 32 + NT - 1) / NT;
        k_hsum<<<blocks, NT>>>(sph, w1, b1, E2);
    }

    // 7. fused m-GEMM + gate GEMMs + output
    k_final<<<(E2 + 63) / 64, NT, fsmem>>>(t_e2, w2, b2, wgw, bgw, wgt, bgt, E2,
                                           (float*)d_out);
}

// round 4
// speedup vs baseline: 2.6874x; 1.6718x over previous
#include <cuda_runtime.h>

#define H     128
#define NT    256
#define NMAX  10001
#define E1MAX 80000
#define E2MAX 80000
#define WCAP  (E1MAX*16)

// ------- scratch (static device globals; no runtime allocation) ----------
__device__ int   g_ptr[NMAX + 2];
__device__ int   g_cnt[E2MAX];
__device__ int   g_part[128];
__device__ int   g_wptr[E2MAX + 1];
__device__ int   g_weik[WCAP];
__device__ int   g_wekj[WCAP];
__device__ float g_U[(size_t)E1MAX * H];
__device__ float g_V[(size_t)E1MAX * H];
__device__ float g_Z[(size_t)E2MAX * H];
__device__ float g_S[(size_t)E2MAX * H];

// ------------------------- helpers ---------------------------------------
__device__ __forceinline__ float to_tf32(float x) {
    unsigned u;
    asm("cvt.rna.tf32.f32 %0, %1;" : "=r"(u) : "f"(x));
    return __uint_as_float(u);
}

__device__ __forceinline__ void mma_tf32(float c[4], const unsigned a[4],
                                         unsigned b0, unsigned b1) {
    asm volatile(
        "mma.sync.aligned.m16n8k8.row.col.f32.tf32.tf32.f32 "
        "{%0,%1,%2,%3}, {%4,%5,%6,%7}, {%8,%9}, {%0,%1,%2,%3};"
        : "+f"(c[0]), "+f"(c[1]), "+f"(c[2]), "+f"(c[3])
        : "r"(a[0]), "r"(a[1]), "r"(a[2]), "r"(a[3]), "r"(b0), "r"(b1));
}

__device__ __forceinline__ void cpa16(void* sdst, const void* gsrc) {
    unsigned s = (unsigned)__cvta_generic_to_shared(sdst);
    asm volatile("cp.async.cg.shared.global [%0], [%1], 16;\n" :: "r"(s), "l"(gsrc));
}
#define CP_COMMIT() asm volatile("cp.async.commit_group;\n")
#define CP_WAIT0()  asm volatile("cp.async.wait_group 0;\n")
#define CP_WAIT1()  asm volatile("cp.async.wait_group 1;\n")

// ---------------- CSR ptr: g_ptr[v] = lower_bound(src1, v) ---------------
__global__ void k_ptr(const int* __restrict__ src1, int E1, const int* __restrict__ nn_p) {
    int v = blockIdx.x * blockDim.x + threadIdx.x;
    int nn = *nn_p;
    if (v > nn || v > NMAX) return;
    int lo = 0, hi = E1;
    while (lo < hi) { int mid = (lo + hi) >> 1; if (src1[mid] < v) lo = mid + 1; else hi = mid; }
    g_ptr[v] = lo;
}

// ------------- per-e2-edge wedge count (sorted-by-eij build) --------------
__global__ void k_count(const int* __restrict__ src2, const int* __restrict__ dst2,
                        const int* __restrict__ dst1, int E2) {
    int q = blockIdx.x * blockDim.x + threadIdx.x;
    if (q >= E2) return;
    int i = src2[q], j = dst2[q];
    int c = 0;
    if (i != j) {
        int b0 = g_ptr[i], e0 = g_ptr[i + 1];
        for (int t = b0; t < e0; t++) {
            int k = dst1[t];
            if (k == i || k == j) continue;
            int b1 = g_ptr[k], e1 = g_ptr[k + 1];
            for (int u = b1; u < e1; u++)
                if (dst1[u] == j) c++;
        }
    }
    g_cnt[q] = c;
}

// ----------------------- 3-phase exclusive scan ---------------------------
__global__ void k_scan_part(int n) {
    int blk = blockIdx.x, tid = threadIdx.x, lane = tid & 31, wid = tid >> 5;
    int base = blk * 2048 + tid * 8;
    int s = 0;
#pragma unroll
    for (int i = 0; i < 8; i++) { int idx = base + i; if (idx < n) s += g_cnt[idx]; }
#pragma unroll
    for (int off = 16; off > 0; off >>= 1) s += __shfl_down_sync(0xffffffffu, s, off);
    __shared__ int red[8];
    if (lane == 0) red[wid] = s;
    __syncthreads();
    if (tid == 0) {
        int tot = 0;
#pragma unroll
        for (int w = 0; w < 8; w++) tot += red[w];
        g_part[blk] = tot;
    }
}
__global__ void k_scan_top(int nb, int n) {
    if (threadIdx.x == 0) {
        int acc = 0;
        for (int b = 0; b < nb; b++) { int v = g_part[b]; g_part[b] = acc; acc += v; }
        g_wptr[n] = acc;
    }
}
__global__ void k_scan_write(int n) {
    int blk = blockIdx.x, tid = threadIdx.x, lane = tid & 31, wid = tid >> 5;
    int base = blk * 2048 + tid * 8;
    int v[8]; int s = 0;
#pragma unroll
    for (int i = 0; i < 8; i++) {
        int idx = base + i;
        v[i] = (idx < n) ? g_cnt[idx] : 0;
        s += v[i];
    }
    int x = s;
#pragma unroll
    for (int off = 1; off < 32; off <<= 1) {
        int t = __shfl_up_sync(0xffffffffu, x, off);
        if (lane >= off) x += t;
    }
    __shared__ int wsum[8];
    if (lane == 31) wsum[wid] = x;
    __syncthreads();
    __shared__ int wexc[8];
    if (tid == 0) {
        int acc = 0;
#pragma unroll
        for (int w = 0; w < 8; w++) { wexc[w] = acc; acc += wsum[w]; }
    }
    __syncthreads();
    int run = g_part[blk] + wexc[wid] + x - s;
#pragma unroll
    for (int i = 0; i < 8; i++) {
        int idx = base + i;
        if (idx < n) g_wptr[idx] = run;
        run += v[i];
    }
}

__global__ void k_fill(const int* __restrict__ src2, const int* __restrict__ dst2,
                       const int* __restrict__ dst1, int E2) {
    int q = blockIdx.x * blockDim.x + threadIdx.x;
    if (q >= E2) return;
    int i = src2[q], j = dst2[q];
    if (i == j) return;
    int pos = g_wptr[q];
    int b0 = g_ptr[i], e0 = g_ptr[i + 1];
    for (int t = b0; t < e0; t++) {
        int k = dst1[t];
        if (k == i || k == j) continue;
        int b1 = g_ptr[k], e1 = g_ptr[k + 1];
        for (int u = b1; u < e1; u++)
            if (dst1[u] == j) {
                if (pos < WCAP) { g_weik[pos] = t; g_wekj[pos] = u; }
                pos++;
            }
    }
}

// ---------- merged U+V projection (warp-specialized, cp.async pipelined) --
__global__ void __launch_bounds__(256, 2) k_projUV(
    const float* __restrict__ t_e2, const float* __restrict__ h,
    const int* __restrict__ e1e2, const int* __restrict__ src1,
    const int* __restrict__ dst1, const float* __restrict__ rbf1,
    int E1, const float* __restrict__ W,
    float* __restrict__ outU, float* __restrict__ outV) {
    extern __shared__ float sm[];
    float(*As)[64][36]  = (float(*)[64][36])sm;                    // 2 stages
    float(*BU)[32][132] = (float(*)[32][132])(sm + 2 * 64 * 36);
    float(*BV)[32][132] = (float(*)[32][132])(sm + 2 * 64 * 36 + 2 * 32 * 132);
    int* s_row = (int*)(sm + 2 * 64 * 36 + 4 * 32 * 132);          // [4][64]

    int tid = threadIdx.x, lane = tid & 31, wid = tid >> 5;
    int group = wid >> 2;            // 0 = U, 1 = V
    int warp_m = wid & 1;            // 2 row groups of 32
    int warp_n = (wid >> 1) & 1;     // 2 col groups of 64
    int m0 = blockIdx.x * 64;

    for (int r = tid; r < 64; r += 256) {
        int row = m0 + r;
        int rc = (row < E1) ? row : 0;
        s_row[0 * 64 + r] = (row < E1) ? e1e2[row] : 0;
        s_row[1 * 64 + r] = (row < E1) ? src1[row] : 0;
        s_row[2 * 64 + r] = (row < E1) ? dst1[row] : 0;
        s_row[3 * 64 + r] = rc;
    }
    __syncthreads();

    const int wrowU[4] = {0, 384, 512, 768};
    const int wrowV[4] = {128, 0, 640, 800};

    auto copy_chunk = [&](int kc, int st) {
        int seg = kc >> 2;
        int off = (kc & 3) * 32;
        const float* base; int pitch;
        if (seg == 0)      { base = t_e2; pitch = H; }
        else if (seg == 1) { base = h;    pitch = H; }
        else if (seg == 2) { base = h;    pitch = H; }
        else               { base = rbf1; pitch = 32; }
#pragma unroll
        for (int it = 0; it < 2; it++) {
            int pos = tid + it * 256;
            int r = pos >> 3, c4 = pos & 7;
            const float* src = base + (size_t)s_row[seg * 64 + r] * pitch + off + c4 * 4;
            cpa16(&As[st][r][c4 * 4], src);
        }
        const float* WU = W + (size_t)(wrowU[seg] + off) * H;
#pragma unroll
        for (int it = 0; it < 4; it++) {
            int pos = tid + it * 256;
            int r = pos >> 5, c4 = pos & 31;
            cpa16(&BU[st][r][c4 * 4], WU + r * H + c4 * 4);
        }
        if (seg != 1) {
            const float* WV = W + (size_t)(wrowV[seg] + off) * H;
#pragma unroll
            for (int it = 0; it < 4; it++) {
                int pos = tid + it * 256;
                int r = pos >> 5, c4 = pos & 31;
                cpa16(&BV[st][r][c4 * 4], WV + r * H + c4 * 4);
            }
        }
    };

    float C[2][8][4] = {};
    const int TOT = 13;

    copy_chunk(0, 0);
    CP_COMMIT();
    for (int kc = 0; kc < TOT; kc++) {
        if (kc + 1 < TOT) { copy_chunk(kc + 1, (kc + 1) & 1); CP_COMMIT(); CP_WAIT1(); }
        else              { CP_WAIT0(); }
        __syncthreads();
        int st = kc & 1;
        int seg = kc >> 2;
        if (group == 0 || seg != 1) {
            float(*Bsrc)[132] = group ? BV[st] : BU[st];
#pragma unroll
            for (int ks = 0; ks < 4; ks++) {
                int k0 = ks * 8;
                unsigned a[2][4];
#pragma unroll
                for (int mt = 0; mt < 2; mt++) {
                    int rb = warp_m * 32 + mt * 16 + (lane >> 2);
                    int cb = k0 + (lane & 3);
                    a[mt][0] = __float_as_uint(As[st][rb][cb]);
                    a[mt][1] = __float_as_uint(As[st][rb + 8][cb]);
                    a[mt][2] = __float_as_uint(As[st][rb][cb + 4]);
                    a[mt][3] = __float_as_uint(As[st][rb + 8][cb + 4]);
                }
#pragma unroll
                for (int nt = 0; nt < 8; nt++) {
                    int nb = warp_n * 64 + nt * 8 + (lane >> 2);
                    unsigned b0 = __float_as_uint(Bsrc[k0 + (lane & 3)][nb]);
                    unsigned b1 = __float_as_uint(Bsrc[k0 + (lane & 3) + 4][nb]);
                    mma_tf32(C[0][nt], a[0], b0, b1);
                    mma_tf32(C[1][nt], a[1], b0, b1);
                }
            }
        }
        __syncthreads();
    }

    // epilogue (FIXED): C[mt] belongs to row block warp_m*32 + mt*16;
    // c0,c1 -> row (lane>>2), c2,c3 -> row (lane>>2)+8.
    float* outp = group ? outV : outU;
#pragma unroll
    for (int mt = 0; mt < 2; mt++) {
        int r0 = m0 + warp_m * 32 + mt * 16 + (lane >> 2);
#pragma unroll
        for (int nt = 0; nt < 8; nt++) {
            int cb = warp_n * 64 + nt * 8 + 2 * (lane & 3);
            if (r0 < E1)
                *(float2*)&outp[(size_t)r0 * H + cb] =
                    make_float2(C[mt][nt][0], C[mt][nt][1]);
            if (r0 + 8 < E1)
                *(float2*)&outp[(size_t)(r0 + 8) * H + cb] =
                    make_float2(C[mt][nt][2], C[mt][nt][3]);
        }
    }
}

// -------------- generic gathered GEMM (used for Z) ------------------------
struct GSpec {
    const float* base[4];
    const int*   idx[4];
    int          pitch[4];
    int          width[4];
    int          wrow[4];
    int          nseg;
};

__global__ void __launch_bounds__(NT) k_proj(GSpec g, int R, const float* __restrict__ W,
                                             float* __restrict__ out) {
    __shared__ float As[64][33];
    __shared__ float Bs[32][132];
    __shared__ int   s_row[4][64];
    int tid = threadIdx.x, lane = tid & 31, wid = tid >> 5;
    int warp_m = wid & 1, warp_n = wid >> 1;
    int m0 = blockIdx.x * 64;

    for (int s = 0; s < g.nseg; s++)
        for (int r = tid; r < 64; r += NT) {
            int row = m0 + r;
            s_row[s][r] = (row < R) ? (g.idx[s] ? g.idx[s][row] : row) : 0;
        }
    __syncthreads();

    float C[2][4][4] = {};
    int tot = 0;
    for (int s = 0; s < g.nseg; s++) tot += g.width[s] >> 5;

    int seg = 0, segch = 0;
    for (int kc = 0; kc < tot; kc++) {
        int off = segch * 32;
        const float* base = g.base[seg];
        int pitch = g.pitch[seg];
        const float* Wc = W + (size_t)(g.wrow[seg] + off) * H;
#pragma unroll
        for (int it = 0; it < 8; it++) {
            int pos = tid + it * NT;
            int r = pos >> 5, c = pos & 31;
            As[r][c] = to_tf32(base[(size_t)s_row[seg][r] * pitch + off + c]);
        }
#pragma unroll
        for (int it = 0; it < 16; it++) {
            int pos = tid + it * NT;
            int r = pos >> 7, c = pos & 127;
            Bs[r][c] = to_tf32(Wc[pos]);
        }
        __syncthreads();
#pragma unroll
        for (int ks = 0; ks < 4; ks++) {
            int k0 = ks * 8;
            unsigned a[2][4];
#pragma unroll
            for (int mt = 0; mt < 2; mt++) {
                int rb = warp_m * 32 + mt * 16 + (lane >> 2);
                int cb = k0 + (lane & 3);
                a[mt][0] = __float_as_uint(As[rb][cb]);
                a[mt][1] = __float_as_uint(As[rb + 8][cb]);
                a[mt][2] = __float_as_uint(As[rb][cb + 4]);
                a[mt][3] = __float_as_uint(As[rb + 8][cb + 4]);
            }
#pragma unroll
            for (int nt = 0; nt < 4; nt++) {
                int nb = warp_n * 32 + nt * 8 + (lane >> 2);
                unsigned b0 = __float_as_uint(Bs[k0 + (lane & 3)][nb]);
                unsigned b1 = __float_as_uint(Bs[k0 + (lane & 3) + 4][nb]);
                mma_tf32(C[0][nt], a[0], b0, b1);
                mma_tf32(C[1][nt], a[1], b0, b1);
            }
        }
        __syncthreads();
        segch++;
        if ((segch << 5) >= g.width[seg]) { seg++; segch = 0; }
    }

#pragma unroll
    for (int mt = 0; mt < 2; mt++) {
        int r0 = warp_m * 32 + mt * 16 + (lane >> 2);
#pragma unroll
        for (int nt = 0; nt < 4; nt++) {
            int cb = warp_n * 32 + nt * 8 + 2 * (lane & 3);
            int row = m0 + r0;
            if (row < R)
                *(float2*)&out[(size_t)row * H + cb] = make_float2(C[mt][nt][0], C[mt][nt][1]);
            if (row + 8 < R)
                *(float2*)&out[(size_t)(row + 8) * H + cb] = make_float2(C[mt][nt][2], C[mt][nt][3]);
        }
    }
}

// ---- per-e2 hidden sum: S[q] = sum_w silu(U[eik]+V[ekj]+Z[q]+c*w864+b1) ---
__global__ void __launch_bounds__(NT) k_hsum(const float* __restrict__ sph,
                                             const float* __restrict__ w1,
                                             const float* __restrict__ b1, int E2) {
    int warp = (blockIdx.x * blockDim.x + threadIdx.x) >> 5;
    int lane = threadIdx.x & 31;
    if (warp >= E2) return;
    int q = warp;
    int beg = g_wptr[q], end = g_wptr[q + 1];
    if (beg > WCAP) beg = WCAP;
    if (end > WCAP) end = WCAP;
    float4 z  = *(const float4*)&g_Z[(size_t)q * H + lane * 4];
    float4 w8 = *(const float4*)&w1[(size_t)864 * H + lane * 4];
    float4 bb = *(const float4*)&b1[lane * 4];
    float4 acc = make_float4(0.f, 0.f, 0.f, 0.f);

    float4 u, v; float cf = 0.f;
    int w = beg;
    if (w < end) {
        int a = g_weik[w], b = g_wekj[w];
        cf = __ldg(&sph[a * 3 + 1]) * __ldg(&sph[b * 3 + 1]);
        u = *(const float4*)&g_U[(size_t)a * H + lane * 4];
        v = *(const float4*)&g_V[(size_t)b * H + lane * 4];
    }
    while (w < end) {
        float4 cu = u, cv = v; float c0 = cf;
        int nw = w + 1;
        if (nw < end) {
            int a = g_weik[nw], b = g_wekj[nw];
            cf = __ldg(&sph[a * 3 + 1]) * __ldg(&sph[b * 3 + 1]);
            u = *(const float4*)&g_U[(size_t)a * H + lane * 4];
            v = *(const float4*)&g_V[(size_t)b * H + lane * 4];
        }
        float x;
        x = cu.x + cv.x + z.x + c0 * w8.x + bb.x; acc.x += x / (1.f + __expf(-x));
        x = cu.y + cv.y + z.y + c0 * w8.y + bb.y; acc.y += x / (1.f + __expf(-x));
        x = cu.z + cv.z + z.z + c0 * w8.z + bb.z; acc.z += x / (1.f + __expf(-x));
        x = cu.w + cv.w + z.w + c0 * w8.w + bb.w; acc.w += x / (1.f + __expf(-x));
        w = nw;
    }
    *(float4*)&g_S[(size_t)q * H + lane * 4] = acc;
}

// ---- fused: m = S@W2 + cnt*b2; out = t + sigmoid(m@wgw+bgw)*tanh(t@wgt+bgt)
__global__ void __launch_bounds__(NT) k_final(const float* __restrict__ t_e2,
                                              const float* __restrict__ w2,
                                              const float* __restrict__ b2,
                                              const float* __restrict__ wgw,
                                              const float* __restrict__ bgw,
                                              const float* __restrict__ wgt,
                                              const float* __restrict__ bgt,
                                              int E2, float* __restrict__ out) {
    extern __shared__ float sm[];
    float(*Ss)[132] = (float(*)[132])sm;
    float(*Ms)[132] = (float(*)[132])(sm + 64 * 132);
    float(*Bs)[132] = (float(*)[132])(sm + 2 * 64 * 132);
    __shared__ int s_cnt[64];

    int tid = threadIdx.x, lane = tid & 31, wid = tid >> 5;
    int warp_m = wid & 1, warp_n = wid >> 1;
    int m0 = blockIdx.x * 64;

    for (int r = tid; r < 64; r += NT) {
        int row = m0 + r;
        s_cnt[r] = (row < E2) ? (g_wptr[row + 1] - g_wptr[row]) : 0;
    }
#pragma unroll
    for (int it = 0; it < 8; it++) {
        int pos = tid + it * NT;
        int r = pos >> 5, c4 = pos & 31;
        int row = m0 + r;
        float4 v = (row < E2) ? *(const float4*)&g_S[(size_t)row * H + c4 * 4]
                              : make_float4(0.f, 0.f, 0.f, 0.f);
        Ss[r][c4 * 4 + 0] = to_tf32(v.x);
        Ss[r][c4 * 4 + 1] = to_tf32(v.y);
        Ss[r][c4 * 4 + 2] = to_tf32(v.z);
        Ss[r][c4 * 4 + 3] = to_tf32(v.w);
    }
    __syncthreads();

    float C[2][4][4] = {};
    for (int kc = 0; kc < 4; kc++) {
        const float* Wc = w2 + (size_t)kc * 32 * H;
#pragma unroll
        for (int it = 0; it < 16; it++) {
            int pos = tid + it * NT;
            int r = pos >> 7, c = pos & 127;
            Bs[r][c] = to_tf32(Wc[pos]);
        }
        __syncthreads();
#pragma unroll
        for (int ks = 0; ks < 4; ks++) {
            int k0 = kc * 32 + ks * 8;
            int kb = ks * 8;
            unsigned a[2][4];
#pragma unroll
            for (int mt = 0; mt < 2; mt++) {
                int rb = warp_m * 32 + mt * 16 + (lane >> 2);
                int cb = k0 + (lane & 3);
                a[mt][0] = __float_as_uint(Ss[rb][cb]);
                a[mt][1] = __float_as_uint(Ss[rb + 8][cb]);
                a[mt][2] = __float_as_uint(Ss[rb][cb + 4]);
                a[mt][3] = __float_as_uint(Ss[rb + 8][cb + 4]);
            }
#pragma unroll
            for (int nt = 0; nt < 4; nt++) {
                int nb = warp_n * 32 + nt * 8 + (lane >> 2);
                unsigned b0 = __float_as_uint(Bs[kb + (lane & 3)][nb]);
                unsigned b1 = __float_as_uint(Bs[kb + (lane & 3) + 4][nb]);
                mma_tf32(C[0][nt], a[0], b0, b1);
                mma_tf32(C[1][nt], a[1], b0, b1);
            }
        }
        __syncthreads();
    }

#pragma unroll
    for (int mt = 0; mt < 2; mt++) {
        int r0 = warp_m * 32 + mt * 16 + (lane >> 2);
        float cn0 = (float)s_cnt[r0], cn1 = (float)s_cnt[r0 + 8];
#pragma unroll
        for (int nt = 0; nt < 4; nt++) {
            int cb = warp_n * 32 + nt * 8 + 2 * (lane & 3);
            Ms[r0][cb]         = to_tf32(C[mt][nt][0] + cn0 * b2[cb]);
            Ms[r0][cb + 1]     = to_tf32(C[mt][nt][1] + cn0 * b2[cb + 1]);
            Ms[r0 + 8][cb]     = to_tf32(C[mt][nt][2] + cn1 * b2[cb]);
            Ms[r0 + 8][cb + 1] = to_tf32(C[mt][nt][3] + cn1 * b2[cb + 1]);
        }
    }
#pragma unroll
    for (int it = 0; it < 8; it++) {
        int pos = tid + it * NT;
        int r = pos >> 5, c4 = pos & 31;
        int row = m0 + r;
        float4 v = (row < E2) ? *(const float4*)&t_e2[(size_t)row * H + c4 * 4]
                              : make_float4(0.f, 0.f, 0.f, 0.f);
        Ss[r][c4 * 4 + 0] = to_tf32(v.x);
        Ss[r][c4 * 4 + 1] = to_tf32(v.y);
        Ss[r][c4 * 4 + 2] = to_tf32(v.z);
        Ss[r][c4 * 4 + 3] = to_tf32(v.w);
    }
    __syncthreads();

    float C2[2][4][4] = {};
    for (int kc = 0; kc < 4; kc++) {
        const float* Wc = wgw + (size_t)kc * 32 * H;
#pragma unroll
        for (int it = 0; it < 16; it++) {
            int pos = tid + it * NT;
            int r = pos >> 7, c = pos & 127;
            Bs[r][c] = to_tf32(Wc[pos]);
        }
        __syncthreads();
#pragma unroll
        for (int ks = 0; ks < 4; ks++) {
            int k0 = kc * 32 + ks * 8;
            int kb = ks * 8;
            unsigned a[2][4];
#pragma unroll
            for (int mt = 0; mt < 2; mt++) {
                int rb = warp_m * 32 + mt * 16 + (lane >> 2);
                int cb = k0 + (lane & 3);
                a[mt][0] = __float_as_uint(Ms[rb][cb]);
                a[mt][1] = __float_as_uint(Ms[rb + 8][cb]);
                a[mt][2] = __float_as_uint(Ms[rb][cb + 4]);
                a[mt][3] = __float_as_uint(Ms[rb + 8][cb + 4]);
            }
#pragma unroll
            for (int nt = 0; nt < 4; nt++) {
                int nb = warp_n * 32 + nt * 8 + (lane >> 2);
                unsigned b0 = __float_as_uint(Bs[kb + (lane & 3)][nb]);
                unsigned b1 = __float_as_uint(Bs[kb + (lane & 3) + 4][nb]);
                mma_tf32(C2[0][nt], a[0], b0, b1);
                mma_tf32(C2[1][nt], a[1], b0, b1);
            }
        }
        __syncthreads();
    }

    float C3[2][4][4] = {};
    for (int kc = 0; kc < 4; kc++) {
        const float* Wc = wgt + (size_t)kc * 32 * H;
#pragma unroll
        for (int it = 0; it < 16; it++) {
            int pos = tid + it * NT;
            int r = pos >> 7, c = pos & 127;
            Bs[r][c] = to_tf32(Wc[pos]);
        }
        __syncthreads();
#pragma unroll
        for (int ks = 0; ks < 4; ks++) {
            int k0 = kc * 32 + ks * 8;
            int kb = ks * 8;
            unsigned a[2][4];
#pragma unroll
            for (int mt = 0; mt < 2; mt++) {
                int rb = warp_m * 32 + mt * 16 + (lane >> 2);
                int cb = k0 + (lane & 3);
                a[mt][0] = __float_as_uint(Ss[rb][cb]);
                a[mt][1] = __float_as_uint(Ss[rb + 8][cb]);
                a[mt][2] = __float_as_uint(Ss[rb][cb + 4]);
                a[mt][3] = __float_as_uint(Ss[rb + 8][cb + 4]);
            }
#pragma unroll
            for (int nt = 0; nt < 4; nt++) {
                int nb = warp_n * 32 + nt * 8 + (lane >> 2);
                unsigned b0 = __float_as_uint(Bs[kb + (lane & 3)][nb]);
                unsigned b1 = __float_as_uint(Bs[kb + (lane & 3) + 4][nb]);
                mma_tf32(C3[0][nt], a[0], b0, b1);
                mma_tf32(C3[1][nt], a[1], b0, b1);
            }
        }
        __syncthreads();
    }

#pragma unroll
    for (int mt = 0; mt < 2; mt++) {
        int r0 = warp_m * 32 + mt * 16 + (lane >> 2);
#pragma unroll
        for (int nt = 0; nt < 4; nt++) {
            int cb = warp_n * 32 + nt * 8 + 2 * (lane & 3);
#pragma unroll
            for (int half = 0; half < 2; half++) {
                int row = m0 + r0 + half * 8;
                if (row >= E2) continue;
#pragma unroll
                for (int e = 0; e < 2; e++) {
                    int col = cb + e;
                    float gw = C2[mt][nt][half * 2 + e] + bgw[col];
                    float gt = C3[mt][nt][half * 2 + e] + bgt[col];
                    float sig = 1.f / (1.f + __expf(-gw));
                    out[(size_t)row * H + col] =
                        t_e2[(size_t)row * H + col] + sig * tanhf(gt);
                }
            }
        }
    }
}

// --------------------------------------------------------------------------
extern "C" void kernel_launch(void* const* d_in, const int* in_sizes, int n_in,
                              void* d_out, int out_size) {
    const float* t_e2 = (const float*)d_in[0];
    const float* h    = (const float*)d_in[1];
    const int*   ei1  = (const int*)d_in[2];
    const int*   ei2  = (const int*)d_in[3];
    const int*   e1e2 = (const int*)d_in[4];
    const float* rbf1 = (const float*)d_in[7];
    const float* rbf2 = (const float*)d_in[8];
    const float* sph  = (const float*)d_in[9];
    const int*   nn_p = (const int*)d_in[10];
    const float* w1   = (const float*)d_in[11];
    const float* b1   = (const float*)d_in[12];
    const float* w2   = (const float*)d_in[13];
    const float* b2   = (const float*)d_in[14];
    const float* wgw  = (const float*)d_in[15];
    const float* bgw  = (const float*)d_in[16];
    const float* wgt  = (const float*)d_in[17];
    const float* bgt  = (const float*)d_in[18];

    int E1 = in_sizes[4];
    int E2 = in_sizes[0] / H;
    const int* src1 = ei1;
    const int* dst1 = ei1 + E1;
    const int* src2 = ei2;
    const int* dst2 = ei2 + E2;

    float *pU, *pV, *pZ;
    cudaGetSymbolAddress((void**)&pU, g_U);
    cudaGetSymbolAddress((void**)&pV, g_V);
    cudaGetSymbolAddress((void**)&pZ, g_Z);

    size_t fsmem = (size_t)(2 * 64 * 132 + 32 * 132) * 4;
    cudaFuncSetAttribute(k_final, cudaFuncAttributeMaxDynamicSharedMemorySize, (int)fsmem);
    size_t uvsmem = (size_t)(2 * 64 * 36 + 4 * 32 * 132) * 4 + 4 * 64 * sizeof(int);
    cudaFuncSetAttribute(k_projUV, cudaFuncAttributeMaxDynamicSharedMemorySize, (int)uvsmem);

    // 1. CSR ptr
    k_ptr<<<(NMAX + 1 + NT - 1) / NT, NT>>>(src1, E1, nn_p);
    // 2-4. wedge lists grouped by e2 edge: count -> scan(3 phase) -> fill
    k_count<<<(E2 + NT - 1) / NT, NT>>>(src2, dst2, dst1, E2);
    int nscan = (E2 + 2047) / 2048;
    k_scan_part<<<nscan, NT>>>(E2);
    k_scan_top<<<1, 32>>>(nscan, E2);
    k_scan_write<<<nscan, NT>>>(E2);
    k_fill<<<(E2 + NT - 1) / NT, NT>>>(src2, dst2, dst1, E2);

    // 5. projections: merged U+V (pipelined), Z (generic)
    k_projUV<<<(E1 + 63) / 64, 256, uvsmem>>>(t_e2, h, e1e2, src1, dst1, rbf1,
                                              E1, w1, pU, pV);
    {
        GSpec gz;
        gz.nseg = 2;
        gz.base[0] = t_e2; gz.idx[0] = nullptr; gz.pitch[0] = H;  gz.width[0] = 128; gz.wrow[0] = 256;
        gz.base[1] = rbf2; gz.idx[1] = nullptr; gz.pitch[1] = 32; gz.width[1] = 32;  gz.wrow[1] = 832;
        gz.base[2] = t_e2; gz.idx[2] = nullptr; gz.pitch[2] = H;  gz.width[2] = 0;   gz.wrow[2] = 0;
        gz.base[3] = t_e2; gz.idx[3] = nullptr; gz.pitch[3] = H;  gz.width[3] = 0;   gz.wrow[3] = 0;
        k_proj<<<(E2 + 63) / 64, NT>>>(gz, E2, w1, pZ);
    }

    // 6. per-e2 hidden sum (atomic-free, prefetched)
    {
        int blocks = (E2 * 32 + NT - 1) / NT;
        k_hsum<<<blocks, NT>>>(sph, w1, b1, E2);
    }

    // 7. fused m-GEMM + gate GEMMs + output
    k_final<<<(E2 + 63) / 64, NT, fsmem>>>(t_e2, w2, b2, wgw, bgw, wgt, bgt, E2,
                                           (float*)d_out);
}

// round 5
// speedup vs baseline: 2.9126x; 1.0838x over previous
#include <cuda_runtime.h>

#define H     128
#define NT    256
#define NMAX  10001
#define E1MAX 80000
#define E2MAX 80000
#define WCAP  (E1MAX*16)

// ------- scratch (static device globals; no runtime allocation) ----------
__device__ int   g_ptr[NMAX + 2];
__device__ int   g_cnt[E2MAX];
__device__ int   g_part[128];
__device__ int   g_wptr[E2MAX + 1];
__device__ int   g_weik[WCAP];
__device__ int   g_wekj[WCAP];
__device__ float g_U[(size_t)E1MAX * H];
__device__ float g_V[(size_t)E1MAX * H];
__device__ float g_Z[(size_t)E2MAX * H];
__device__ float g_S[(size_t)E2MAX * H];

// ------------------------- helpers ---------------------------------------
__device__ __forceinline__ float to_tf32(float x) {
    unsigned u;
    asm("cvt.rna.tf32.f32 %0, %1;" : "=r"(u) : "f"(x));
    return __uint_as_float(u);
}

__device__ __forceinline__ void mma_tf32(float c[4], const unsigned a[4],
                                         unsigned b0, unsigned b1) {
    asm volatile(
        "mma.sync.aligned.m16n8k8.row.col.f32.tf32.tf32.f32 "
        "{%0,%1,%2,%3}, {%4,%5,%6,%7}, {%8,%9}, {%0,%1,%2,%3};"
        : "+f"(c[0]), "+f"(c[1]), "+f"(c[2]), "+f"(c[3])
        : "r"(a[0]), "r"(a[1]), "r"(a[2]), "r"(a[3]), "r"(b0), "r"(b1));
}

__device__ __forceinline__ void cpa16(void* sdst, const void* gsrc) {
    unsigned s = (unsigned)__cvta_generic_to_shared(sdst);
    asm volatile("cp.async.cg.shared.global [%0], [%1], 16;\n" :: "r"(s), "l"(gsrc));
}
#define CP_COMMIT() asm volatile("cp.async.commit_group;\n")
#define CP_WAIT0()  asm volatile("cp.async.wait_group 0;\n")
#define CP_WAIT1()  asm volatile("cp.async.wait_group 1;\n")

// ---------------- CSR ptr: g_ptr[v] = lower_bound(src1, v) ---------------
__global__ void k_ptr(const int* __restrict__ src1, int E1, const int* __restrict__ nn_p) {
    int v = blockIdx.x * blockDim.x + threadIdx.x;
    int nn = *nn_p;
    if (v > nn || v > NMAX) return;
    int lo = 0, hi = E1;
    while (lo < hi) { int mid = (lo + hi) >> 1; if (src1[mid] < v) lo = mid + 1; else hi = mid; }
    g_ptr[v] = lo;
}

// ------------- per-e2-edge wedge count (sorted-by-eij build) --------------
__global__ void k_count(const int* __restrict__ src2, const int* __restrict__ dst2,
                        const int* __restrict__ dst1, int E2) {
    int q = blockIdx.x * blockDim.x + threadIdx.x;
    if (q >= E2) return;
    int i = src2[q], j = dst2[q];
    int c = 0;
    if (i != j) {
        int b0 = g_ptr[i], e0 = g_ptr[i + 1];
        for (int t = b0; t < e0; t++) {
            int k = dst1[t];
            if (k == i || k == j) continue;
            int b1 = g_ptr[k], e1 = g_ptr[k + 1];
            for (int u = b1; u < e1; u++)
                if (dst1[u] == j) c++;
        }
    }
    g_cnt[q] = c;
}

// ----------------------- 3-phase exclusive scan ---------------------------
__global__ void k_scan_part(int n) {
    int blk = blockIdx.x, tid = threadIdx.x, lane = tid & 31, wid = tid >> 5;
    int base = blk * 2048 + tid * 8;
    int s = 0;
#pragma unroll
    for (int i = 0; i < 8; i++) { int idx = base + i; if (idx < n) s += g_cnt[idx]; }
#pragma unroll
    for (int off = 16; off > 0; off >>= 1) s += __shfl_down_sync(0xffffffffu, s, off);
    __shared__ int red[8];
    if (lane == 0) red[wid] = s;
    __syncthreads();
    if (tid == 0) {
        int tot = 0;
#pragma unroll
        for (int w = 0; w < 8; w++) tot += red[w];
        g_part[blk] = tot;
    }
}
__global__ void k_scan_top(int nb, int n) {
    if (threadIdx.x == 0) {
        int acc = 0;
        for (int b = 0; b < nb; b++) { int v = g_part[b]; g_part[b] = acc; acc += v; }
        g_wptr[n] = acc;
    }
}
__global__ void k_scan_write(int n) {
    int blk = blockIdx.x, tid = threadIdx.x, lane = tid & 31, wid = tid >> 5;
    int base = blk * 2048 + tid * 8;
    int v[8]; int s = 0;
#pragma unroll
    for (int i = 0; i < 8; i++) {
        int idx = base + i;
        v[i] = (idx < n) ? g_cnt[idx] : 0;
        s += v[i];
    }
    int x = s;
#pragma unroll
    for (int off = 1; off < 32; off <<= 1) {
        int t = __shfl_up_sync(0xffffffffu, x, off);
        if (lane >= off) x += t;
    }
    __shared__ int wsum[8];
    if (lane == 31) wsum[wid] = x;
    __syncthreads();
    __shared__ int wexc[8];
    if (tid == 0) {
        int acc = 0;
#pragma unroll
        for (int w = 0; w < 8; w++) { wexc[w] = acc; acc += wsum[w]; }
    }
    __syncthreads();
    int run = g_part[blk] + wexc[wid] + x - s;
#pragma unroll
    for (int i = 0; i < 8; i++) {
        int idx = base + i;
        if (idx < n) g_wptr[idx] = run;
        run += v[i];
    }
}

__global__ void k_fill(const int* __restrict__ src2, const int* __restrict__ dst2,
                       const int* __restrict__ dst1, int E2) {
    int q = blockIdx.x * blockDim.x + threadIdx.x;
    if (q >= E2) return;
    int i = src2[q], j = dst2[q];
    if (i == j) return;
    int pos = g_wptr[q];
    int b0 = g_ptr[i], e0 = g_ptr[i + 1];
    for (int t = b0; t < e0; t++) {
        int k = dst1[t];
        if (k == i || k == j) continue;
        int b1 = g_ptr[k], e1 = g_ptr[k + 1];
        for (int u = b1; u < e1; u++)
            if (dst1[u] == j) {
                if (pos < WCAP) { g_weik[pos] = t; g_wekj[pos] = u; }
                pos++;
            }
    }
}

// ---------- merged U+V projection (warp-specialized, cp.async pipelined) --
__global__ void __launch_bounds__(256, 2) k_projUV(
    const float* __restrict__ t_e2, const float* __restrict__ h,
    const int* __restrict__ e1e2, const int* __restrict__ src1,
    const int* __restrict__ dst1, const float* __restrict__ rbf1,
    int E1, const float* __restrict__ W,
    float* __restrict__ outU, float* __restrict__ outV) {
    extern __shared__ float sm[];
    float(*As)[64][36]  = (float(*)[64][36])sm;                    // 2 stages
    float(*BU)[32][132] = (float(*)[32][132])(sm + 2 * 64 * 36);
    float(*BV)[32][132] = (float(*)[32][132])(sm + 2 * 64 * 36 + 2 * 32 * 132);
    int* s_row = (int*)(sm + 2 * 64 * 36 + 4 * 32 * 132);          // [4][64]

    int tid = threadIdx.x, lane = tid & 31, wid = tid >> 5;
    int group = wid >> 2;            // 0 = U, 1 = V
    int warp_m = wid & 1;            // 2 row groups of 32
    int warp_n = (wid >> 1) & 1;     // 2 col groups of 64
    int m0 = blockIdx.x * 64;

    for (int r = tid; r < 64; r += 256) {
        int row = m0 + r;
        int rc = (row < E1) ? row : 0;
        s_row[0 * 64 + r] = (row < E1) ? e1e2[row] : 0;
        s_row[1 * 64 + r] = (row < E1) ? src1[row] : 0;
        s_row[2 * 64 + r] = (row < E1) ? dst1[row] : 0;
        s_row[3 * 64 + r] = rc;
    }
    __syncthreads();

    const int wrowU[4] = {0, 384, 512, 768};
    const int wrowV[4] = {128, 0, 640, 800};

    auto copy_chunk = [&](int kc, int st) {
        int seg = kc >> 2;
        int off = (kc & 3) * 32;
        const float* base; int pitch;
        if (seg == 0)      { base = t_e2; pitch = H; }
        else if (seg == 1) { base = h;    pitch = H; }
        else if (seg == 2) { base = h;    pitch = H; }
        else               { base = rbf1; pitch = 32; }
#pragma unroll
        for (int it = 0; it < 2; it++) {
            int pos = tid + it * 256;
            int r = pos >> 3, c4 = pos & 7;
            const float* src = base + (size_t)s_row[seg * 64 + r] * pitch + off + c4 * 4;
            cpa16(&As[st][r][c4 * 4], src);
        }
        const float* WU = W + (size_t)(wrowU[seg] + off) * H;
#pragma unroll
        for (int it = 0; it < 4; it++) {
            int pos = tid + it * 256;
            int r = pos >> 5, c4 = pos & 31;
            cpa16(&BU[st][r][c4 * 4], WU + r * H + c4 * 4);
        }
        if (seg != 1) {
            const float* WV = W + (size_t)(wrowV[seg] + off) * H;
#pragma unroll
            for (int it = 0; it < 4; it++) {
                int pos = tid + it * 256;
                int r = pos >> 5, c4 = pos & 31;
                cpa16(&BV[st][r][c4 * 4], WV + r * H + c4 * 4);
            }
        }
    };

    float C[2][8][4] = {};
    const int TOT = 13;

    copy_chunk(0, 0);
    CP_COMMIT();
    for (int kc = 0; kc < TOT; kc++) {
        if (kc + 1 < TOT) { copy_chunk(kc + 1, (kc + 1) & 1); CP_COMMIT(); CP_WAIT1(); }
        else              { CP_WAIT0(); }
        __syncthreads();
        int st = kc & 1;
        int seg = kc >> 2;
        if (group == 0 || seg != 1) {
            float(*Bsrc)[132] = group ? BV[st] : BU[st];
#pragma unroll
            for (int ks = 0; ks < 4; ks++) {
                int k0 = ks * 8;
                unsigned a[2][4];
#pragma unroll
                for (int mt = 0; mt < 2; mt++) {
                    int rb = warp_m * 32 + mt * 16 + (lane >> 2);
                    int cb = k0 + (lane & 3);
                    a[mt][0] = __float_as_uint(As[st][rb][cb]);
                    a[mt][1] = __float_as_uint(As[st][rb + 8][cb]);
                    a[mt][2] = __float_as_uint(As[st][rb][cb + 4]);
                    a[mt][3] = __float_as_uint(As[st][rb + 8][cb + 4]);
                }
#pragma unroll
                for (int nt = 0; nt < 8; nt++) {
                    int nb = warp_n * 64 + nt * 8 + (lane >> 2);
                    unsigned b0 = __float_as_uint(Bsrc[k0 + (lane & 3)][nb]);
                    unsigned b1 = __float_as_uint(Bsrc[k0 + (lane & 3) + 4][nb]);
                    mma_tf32(C[0][nt], a[0], b0, b1);
                    mma_tf32(C[1][nt], a[1], b0, b1);
                }
            }
        }
        __syncthreads();
    }

    float* outp = group ? outV : outU;
#pragma unroll
    for (int mt = 0; mt < 2; mt++) {
        int r0 = m0 + warp_m * 32 + mt * 16 + (lane >> 2);
#pragma unroll
        for (int nt = 0; nt < 8; nt++) {
            int cb = warp_n * 64 + nt * 8 + 2 * (lane & 3);
            if (r0 < E1)
                *(float2*)&outp[(size_t)r0 * H + cb] =
                    make_float2(C[mt][nt][0], C[mt][nt][1]);
            if (r0 + 8 < E1)
                *(float2*)&outp[(size_t)(r0 + 8) * H + cb] =
                    make_float2(C[mt][nt][2], C[mt][nt][3]);
        }
    }
}

// -------------- generic gathered GEMM (used for Z) ------------------------
struct GSpec {
    const float* base[4];
    const int*   idx[4];
    int          pitch[4];
    int          width[4];
    int          wrow[4];
    int          nseg;
};

__global__ void __launch_bounds__(NT) k_proj(GSpec g, int R, const float* __restrict__ W,
                                             float* __restrict__ out) {
    __shared__ float As[64][33];
    __shared__ float Bs[32][132];
    __shared__ int   s_row[4][64];
    int tid = threadIdx.x, lane = tid & 31, wid = tid >> 5;
    int warp_m = wid & 1, warp_n = wid >> 1;
    int m0 = blockIdx.x * 64;

    for (int s = 0; s < g.nseg; s++)
        for (int r = tid; r < 64; r += NT) {
            int row = m0 + r;
            s_row[s][r] = (row < R) ? (g.idx[s] ? g.idx[s][row] : row) : 0;
        }
    __syncthreads();

    float C[2][4][4] = {};
    int tot = 0;
    for (int s = 0; s < g.nseg; s++) tot += g.width[s] >> 5;

    int seg = 0, segch = 0;
    for (int kc = 0; kc < tot; kc++) {
        int off = segch * 32;
        const float* base = g.base[seg];
        int pitch = g.pitch[seg];
        const float* Wc = W + (size_t)(g.wrow[seg] + off) * H;
#pragma unroll
        for (int it = 0; it < 8; it++) {
            int pos = tid + it * NT;
            int r = pos >> 5, c = pos & 31;
            As[r][c] = to_tf32(base[(size_t)s_row[seg][r] * pitch + off + c]);
        }
#pragma unroll
        for (int it = 0; it < 16; it++) {
            int pos = tid + it * NT;
            int r = pos >> 7, c = pos & 127;
            Bs[r][c] = to_tf32(Wc[pos]);
        }
        __syncthreads();
#pragma unroll
        for (int ks = 0; ks < 4; ks++) {
            int k0 = ks * 8;
            unsigned a[2][4];
#pragma unroll
            for (int mt = 0; mt < 2; mt++) {
                int rb = warp_m * 32 + mt * 16 + (lane >> 2);
                int cb = k0 + (lane & 3);
                a[mt][0] = __float_as_uint(As[rb][cb]);
                a[mt][1] = __float_as_uint(As[rb + 8][cb]);
                a[mt][2] = __float_as_uint(As[rb][cb + 4]);
                a[mt][3] = __float_as_uint(As[rb + 8][cb + 4]);
            }
#pragma unroll
            for (int nt = 0; nt < 4; nt++) {
                int nb = warp_n * 32 + nt * 8 + (lane >> 2);
                unsigned b0 = __float_as_uint(Bs[k0 + (lane & 3)][nb]);
                unsigned b1 = __float_as_uint(Bs[k0 + (lane & 3) + 4][nb]);
                mma_tf32(C[0][nt], a[0], b0, b1);
                mma_tf32(C[1][nt], a[1], b0, b1);
            }
        }
        __syncthreads();
        segch++;
        if ((segch << 5) >= g.width[seg]) { seg++; segch = 0; }
    }

#pragma unroll
    for (int mt = 0; mt < 2; mt++) {
        int r0 = warp_m * 32 + mt * 16 + (lane >> 2);
#pragma unroll
        for (int nt = 0; nt < 4; nt++) {
            int cb = warp_n * 32 + nt * 8 + 2 * (lane & 3);
            int row = m0 + r0;
            if (row < R)
                *(float2*)&out[(size_t)row * H + cb] = make_float2(C[mt][nt][0], C[mt][nt][1]);
            if (row + 8 < R)
                *(float2*)&out[(size_t)(row + 8) * H + cb] = make_float2(C[mt][nt][2], C[mt][nt][3]);
        }
    }
}

// ---- per-e2 hidden sum: S[q] = sum_w silu(U[eik]+V[ekj]+Z[q]+c*w864+b1) ---
__global__ void __launch_bounds__(NT) k_hsum(const float* __restrict__ sph,
                                             const float* __restrict__ w1,
                                             const float* __restrict__ b1, int E2) {
    int warp = (blockIdx.x * blockDim.x + threadIdx.x) >> 5;
    int lane = threadIdx.x & 31;
    if (warp >= E2) return;
    int q = warp;
    int beg = g_wptr[q], end = g_wptr[q + 1];
    if (beg > WCAP) beg = WCAP;
    if (end > WCAP) end = WCAP;
    float4 z  = *(const float4*)&g_Z[(size_t)q * H + lane * 4];
    float4 w8 = *(const float4*)&w1[(size_t)864 * H + lane * 4];
    float4 bb = *(const float4*)&b1[lane * 4];
    float4 acc = make_float4(0.f, 0.f, 0.f, 0.f);

    float4 u, v; float cf = 0.f;
    int w = beg;
    if (w < end) {
        int a = g_weik[w], b = g_wekj[w];
        cf = __ldg(&sph[a * 3 + 1]) * __ldg(&sph[b * 3 + 1]);
        u = *(const float4*)&g_U[(size_t)a * H + lane * 4];
        v = *(const float4*)&g_V[(size_t)b * H + lane * 4];
    }
    while (w < end) {
        float4 cu = u, cv = v; float c0 = cf;
        int nw = w + 1;
        if (nw < end) {
            int a = g_weik[nw], b = g_wekj[nw];
            cf = __ldg(&sph[a * 3 + 1]) * __ldg(&sph[b * 3 + 1]);
            u = *(const float4*)&g_U[(size_t)a * H + lane * 4];
            v = *(const float4*)&g_V[(size_t)b * H + lane * 4];
        }
        float x;
        x = cu.x + cv.x + z.x + c0 * w8.x + bb.x; acc.x += x / (1.f + __expf(-x));
        x = cu.y + cv.y + z.y + c0 * w8.y + bb.y; acc.y += x / (1.f + __expf(-x));
        x = cu.z + cv.z + z.z + c0 * w8.z + bb.z; acc.z += x / (1.f + __expf(-x));
        x = cu.w + cv.w + z.w + c0 * w8.w + bb.w; acc.w += x / (1.f + __expf(-x));
        w = nw;
    }
    *(float4*)&g_S[(size_t)q * H + lane * 4] = acc;
}

// ---- fused: m = S@W2 + cnt*b2; out = t + sigmoid(m@wgw+bgw)*tanh(t@wgt+bgt)
__global__ void __launch_bounds__(NT) k_final(const float* __restrict__ t_e2,
                                              const float* __restrict__ w2,
                                              const float* __restrict__ b2,
                                              const float* __restrict__ wgw,
                                              const float* __restrict__ bgw,
                                              const float* __restrict__ wgt,
                                              const float* __restrict__ bgt,
                                              int E2, float* __restrict__ out) {
    extern __shared__ float sm[];
    float(*Ss)[132] = (float(*)[132])sm;
    float(*Ms)[132] = (float(*)[132])(sm + 64 * 132);
    float(*Bs)[132] = (float(*)[132])(sm + 2 * 64 * 132);
    __shared__ int s_cnt[64];

    int tid = threadIdx.x, lane = tid & 31, wid = tid >> 5;
    int warp_m = wid & 1, warp_n = wid >> 1;
    int m0 = blockIdx.x * 64;

    for (int r = tid; r < 64; r += NT) {
        int row = m0 + r;
        s_cnt[r] = (row < E2) ? (g_wptr[row + 1] - g_wptr[row]) : 0;
    }
#pragma unroll
    for (int it = 0; it < 8; it++) {
        int pos = tid + it * NT;
        int r = pos >> 5, c4 = pos & 31;
        int row = m0 + r;
        float4 v = (row < E2) ? *(const float4*)&g_S[(size_t)row * H + c4 * 4]
                              : make_float4(0.f, 0.f, 0.f, 0.f);
        Ss[r][c4 * 4 + 0] = to_tf32(v.x);
        Ss[r][c4 * 4 + 1] = to_tf32(v.y);
        Ss[r][c4 * 4 + 2] = to_tf32(v.z);
        Ss[r][c4 * 4 + 3] = to_tf32(v.w);
    }
    __syncthreads();

    float C[2][4][4] = {};
    for (int kc = 0; kc < 4; kc++) {
        const float* Wc = w2 + (size_t)kc * 32 * H;
#pragma unroll
        for (int it = 0; it < 16; it++) {
            int pos = tid + it * NT;
            int r = pos >> 7, c = pos & 127;
            Bs[r][c] = to_tf32(Wc[pos]);
        }
        __syncthreads();
#pragma unroll
        for (int ks = 0; ks < 4; ks++) {
            int k0 = kc * 32 + ks * 8;
            int kb = ks * 8;
            unsigned a[2][4];
#pragma unroll
            for (int mt = 0; mt < 2; mt++) {
                int rb = warp_m * 32 + mt * 16 + (lane >> 2);
                int cb = k0 + (lane & 3);
                a[mt][0] = __float_as_uint(Ss[rb][cb]);
                a[mt][1] = __float_as_uint(Ss[rb + 8][cb]);
                a[mt][2] = __float_as_uint(Ss[rb][cb + 4]);
                a[mt][3] = __float_as_uint(Ss[rb + 8][cb + 4]);
            }
#pragma unroll
            for (int nt = 0; nt < 4; nt++) {
                int nb = warp_n * 32 + nt * 8 + (lane >> 2);
                unsigned b0 = __float_as_uint(Bs[kb + (lane & 3)][nb]);
                unsigned b1 = __float_as_uint(Bs[kb + (lane & 3) + 4][nb]);
                mma_tf32(C[0][nt], a[0], b0, b1);
                mma_tf32(C[1][nt], a[1], b0, b1);
            }
        }
        __syncthreads();
    }

#pragma unroll
    for (int mt = 0; mt < 2; mt++) {
        int r0 = warp_m * 32 + mt * 16 + (lane >> 2);
        float cn0 = (float)s_cnt[r0], cn1 = (float)s_cnt[r0 + 8];
#pragma unroll
        for (int nt = 0; nt < 4; nt++) {
            int cb = warp_n * 32 + nt * 8 + 2 * (lane & 3);
            Ms[r0][cb]         = to_tf32(C[mt][nt][0] + cn0 * b2[cb]);
            Ms[r0][cb + 1]     = to_tf32(C[mt][nt][1] + cn0 * b2[cb + 1]);
            Ms[r0 + 8][cb]     = to_tf32(C[mt][nt][2] + cn1 * b2[cb]);
            Ms[r0 + 8][cb + 1] = to_tf32(C[mt][nt][3] + cn1 * b2[cb + 1]);
        }
    }
#pragma unroll
    for (int it = 0; it < 8; it++) {
        int pos = tid + it * NT;
        int r = pos >> 5, c4 = pos & 31;
        int row = m0 + r;
        float4 v = (row < E2) ? *(const float4*)&t_e2[(size_t)row * H + c4 * 4]
                              : make_float4(0.f, 0.f, 0.f, 0.f);
        Ss[r][c4 * 4 + 0] = to_tf32(v.x);
        Ss[r][c4 * 4 + 1] = to_tf32(v.y);
        Ss[r][c4 * 4 + 2] = to_tf32(v.z);
        Ss[r][c4 * 4 + 3] = to_tf32(v.w);
    }
    __syncthreads();

    float C2[2][4][4] = {};
    for (int kc = 0; kc < 4; kc++) {
        const float* Wc = wgw + (size_t)kc * 32 * H;
#pragma unroll
        for (int it = 0; it < 16; it++) {
            int pos = tid + it * NT;
            int r = pos >> 7, c = pos & 127;
            Bs[r][c] = to_tf32(Wc[pos]);
        }
        __syncthreads();
#pragma unroll
        for (int ks = 0; ks < 4; ks++) {
            int k0 = kc * 32 + ks * 8;
            int kb = ks * 8;
            unsigned a[2][4];
#pragma unroll
            for (int mt = 0; mt < 2; mt++) {
                int rb = warp_m * 32 + mt * 16 + (lane >> 2);
                int cb = k0 + (lane & 3);
                a[mt][0] = __float_as_uint(Ms[rb][cb]);
                a[mt][1] = __float_as_uint(Ms[rb + 8][cb]);
                a[mt][2] = __float_as_uint(Ms[rb][cb + 4]);
                a[mt][3] = __float_as_uint(Ms[rb + 8][cb + 4]);
            }
#pragma unroll
            for (int nt = 0; nt < 4; nt++) {
                int nb = warp_n * 32 + nt * 8 + (lane >> 2);
                unsigned b0 = __float_as_uint(Bs[kb + (lane & 3)][nb]);
                unsigned b1 = __float_as_uint(Bs[kb + (lane & 3) + 4][nb]);
                mma_tf32(C2[0][nt], a[0], b0, b1);
                mma_tf32(C2[1][nt], a[1], b0, b1);
            }
        }
        __syncthreads();
    }

    float C3[2][4][4] = {};
    for (int kc = 0; kc < 4; kc++) {
        const float* Wc = wgt + (size_t)kc * 32 * H;
#pragma unroll
        for (int it = 0; it < 16; it++) {
            int pos = tid + it * NT;
            int r = pos >> 7, c = pos & 127;
            Bs[r][c] = to_tf32(Wc[pos]);
        }
        __syncthreads();
#pragma unroll
        for (int ks = 0; ks < 4; ks++) {
            int k0 = kc * 32 + ks * 8;
            int kb = ks * 8;
            unsigned a[2][4];
#pragma unroll
            for (int mt = 0; mt < 2; mt++) {
                int rb = warp_m * 32 + mt * 16 + (lane >> 2);
                int cb = k0 + (lane & 3);
                a[mt][0] = __float_as_uint(Ss[rb][cb]);
                a[mt][1] = __float_as_uint(Ss[rb + 8][cb]);
                a[mt][2] = __float_as_uint(Ss[rb][cb + 4]);
                a[mt][3] = __float_as_uint(Ss[rb + 8][cb + 4]);
            }
#pragma unroll
            for (int nt = 0; nt < 4; nt++) {
                int nb = warp_n * 32 + nt * 8 + (lane >> 2);
                unsigned b0 = __float_as_uint(Bs[kb + (lane & 3)][nb]);
                unsigned b1 = __float_as_uint(Bs[kb + (lane & 3) + 4][nb]);
                mma_tf32(C3[0][nt], a[0], b0, b1);
                mma_tf32(C3[1][nt], a[1], b0, b1);
            }
        }
        __syncthreads();
    }

#pragma unroll
    for (int mt = 0; mt < 2; mt++) {
        int r0 = warp_m * 32 + mt * 16 + (lane >> 2);
#pragma unroll
        for (int nt = 0; nt < 4; nt++) {
            int cb = warp_n * 32 + nt * 8 + 2 * (lane & 3);
#pragma unroll
            for (int half = 0; half < 2; half++) {
                int row = m0 + r0 + half * 8;
                if (row >= E2) continue;
#pragma unroll
                for (int e = 0; e < 2; e++) {
                    int col = cb + e;
                    float gw = C2[mt][nt][half * 2 + e] + bgw[col];
                    float gt = C3[mt][nt][half * 2 + e] + bgt[col];
                    float sig = 1.f / (1.f + __expf(-gw));
                    out[(size_t)row * H + col] =
                        t_e2[(size_t)row * H + col] + sig * tanhf(gt);
                }
            }
        }
    }
}

// --------------------------------------------------------------------------
extern "C" void kernel_launch(void* const* d_in, const int* in_sizes, int n_in,
                              void* d_out, int out_size) {
    const float* t_e2 = (const float*)d_in[0];
    const float* h    = (const float*)d_in[1];
    const int*   ei1  = (const int*)d_in[2];
    const int*   ei2  = (const int*)d_in[3];
    const int*   e1e2 = (const int*)d_in[4];
    const float* rbf1 = (const float*)d_in[7];
    const float* rbf2 = (const float*)d_in[8];
    const float* sph  = (const float*)d_in[9];
    const int*   nn_p = (const int*)d_in[10];
    const float* w1   = (const float*)d_in[11];
    const float* b1   = (const float*)d_in[12];
    const float* w2   = (const float*)d_in[13];
    const float* b2   = (const float*)d_in[14];
    const float* wgw  = (const float*)d_in[15];
    const float* bgw  = (const float*)d_in[16];
    const float* wgt  = (const float*)d_in[17];
    const float* bgt  = (const float*)d_in[18];

    int E1 = in_sizes[4];
    int E2 = in_sizes[0] / H;
    const int* src1 = ei1;
    const int* dst1 = ei1 + E1;
    const int* src2 = ei2;
    const int* dst2 = ei2 + E2;

    float *pU, *pV, *pZ;
    cudaGetSymbolAddress((void**)&pU, g_U);
    cudaGetSymbolAddress((void**)&pV, g_V);
    cudaGetSymbolAddress((void**)&pZ, g_Z);

    size_t fsmem = (size_t)(2 * 64 * 132 + 32 * 132) * 4;
    cudaFuncSetAttribute(k_final, cudaFuncAttributeMaxDynamicSharedMemorySize, (int)fsmem);
    size_t uvsmem = (size_t)(2 * 64 * 36 + 4 * 32 * 132) * 4 + 4 * 64 * sizeof(int);
    cudaFuncSetAttribute(k_projUV, cudaFuncAttributeMaxDynamicSharedMemorySize, (int)uvsmem);

    // lazily created side streams + events (host resources, created once on
    // the first (correctness) call; reused during graph capture where the
    // event record/wait pattern forks/joins capture across streams)
    static cudaStream_t s1 = nullptr, s2 = nullptr;
    static cudaEvent_t evRoot = nullptr, ev1 = nullptr, ev2 = nullptr;
    if (!s1) {
        cudaStreamCreateWithFlags(&s1, cudaStreamNonBlocking);
        cudaStreamCreateWithFlags(&s2, cudaStreamNonBlocking);
        cudaEventCreateWithFlags(&evRoot, cudaEventDisableTiming);
        cudaEventCreateWithFlags(&ev1, cudaEventDisableTiming);
        cudaEventCreateWithFlags(&ev2, cudaEventDisableTiming);
    }

    // ---- fork: projections run concurrently with wedge-list construction --
    cudaEventRecord(evRoot, 0);
    cudaStreamWaitEvent(s1, evRoot, 0);
    cudaStreamWaitEvent(s2, evRoot, 0);

    // s1: merged U+V projection
    k_projUV<<<(E1 + 63) / 64, 256, uvsmem, s1>>>(t_e2, h, e1e2, src1, dst1,
                                                  rbf1, E1, w1, pU, pV);
    cudaEventRecord(ev1, s1);

    // s2: Z projection
    {
        GSpec gz;
        gz.nseg = 2;
        gz.base[0] = t_e2; gz.idx[0] = nullptr; gz.pitch[0] = H;  gz.width[0] = 128; gz.wrow[0] = 256;
        gz.base[1] = rbf2; gz.idx[1] = nullptr; gz.pitch[1] = 32; gz.width[1] = 32;  gz.wrow[1] = 832;
        gz.base[2] = t_e2; gz.idx[2] = nullptr; gz.pitch[2] = H;  gz.width[2] = 0;   gz.wrow[2] = 0;
        gz.base[3] = t_e2; gz.idx[3] = nullptr; gz.pitch[3] = H;  gz.width[3] = 0;   gz.wrow[3] = 0;
        k_proj<<<(E2 + 63) / 64, NT, 0, s2>>>(gz, E2, w1, pZ);
    }
    cudaEventRecord(ev2, s2);

    // default stream: wedge-list construction chain
    k_ptr<<<(NMAX + 1 + NT - 1) / NT, NT>>>(src1, E1, nn_p);
    k_count<<<(E2 + NT - 1) / NT, NT>>>(src2, dst2, dst1, E2);
    int nscan = (E2 + 2047) / 2048;
    k_scan_part<<<nscan, NT>>>(E2);
    k_scan_top<<<1, 32>>>(nscan, E2);
    k_scan_write<<<nscan, NT>>>(E2);
    k_fill<<<(E2 + NT - 1) / NT, NT>>>(src2, dst2, dst1, E2);

    // ---- join ----
    cudaStreamWaitEvent(0, ev1, 0);
    cudaStreamWaitEvent(0, ev2, 0);

    // per-e2 hidden sum (needs U, V, Z, wedge lists)
    {
        int blocks = (E2 * 32 + NT - 1) / NT;
        k_hsum<<<blocks, NT>>>(sph, w1, b1, E2);
    }

    // fused m-GEMM + gate GEMMs + output
    k_final<<<(E2 + 63) / 64, NT, fsmem>>>(t_e2, w2, b2, wgw, bgw, wgt, bgt, E2,
                                           (float*)d_out);
}